// round 9
// baseline (speedup 1.0000x reference)
#include <cuda_runtime.h>
#include <cuda_bf16.h>
#include <cuda_fp16.h>
#include <cstdint>

#define NT   1000
#define NS   2048
#define NH   16
#define NR   8
#define HS   256
#define NG   32
#define NO   48
#define NSNH (NS*NH)
#define TILE_T 128
#define NTILES 8
#define NBLK (NT/8)           // 125
#define STRIDE_H 560          // bytes per 256-fp16 row (conflict-free ldmatrix/LDS)

// ---- dynamic smem byte layout (k_kparam) ----
#define OF_H   0                              // 128 x 560 = 71680
#define OF_W   (OF_H + 128*STRIDE_H)          // 71680, 48 x 560 = 26880
#define OF_FT  (OF_W + 48*STRIDE_H)           // 98560, 128 x 16
#define OF_WZ  (OF_FT + TILE_T*16)            // 100608, 128 x uint4 (packed W_kin half2 pairs)
#define OF_ZB2 (OF_WZ + 128*16)               // 102656, 128 x uint (packed zbase half2)
#define SMEM_BYTES (OF_ZB2 + 512 + 256)       // 103424 -> 2 CTAs/SM

// ---------------- device scratch ----------------
__device__ float g_zbase[NS*HS];
__device__ float g_hg[NS*HS];
__device__ float g_prm[9][NSNH];
__device__ float g_wr[NSNH*NR];
__device__ __half g_k3[(size_t)NS*48*NT];  // [s][c][t]: c 0..15 km, 16..31 ki, 32..47 ke
__device__ float g_Ps[NS*NT];              // [s][t]
__device__ float g_Pl[NS*NT];
__device__ float g_Ev[NS*NT];

__device__ __forceinline__ uint32_t smem_u32(const void* p) {
    uint32_t a;
    asm("{ .reg .u64 t; cvta.to.shared.u64 t, %1; cvt.u32.u64 %0, t; }" : "=r"(a) : "l"(p));
    return a;
}
__device__ __forceinline__ float sigf(float v) { return 1.f / (1.f + expf(-v)); }
__device__ __forceinline__ uint32_t packh2(float a, float b) {
    __half2 p = __floats2half2_rn(a, b);
    return *reinterpret_cast<uint32_t*>(&p);
}
__device__ __forceinline__ float geth(const uint4& v, int i) {
    uint32_t w = (i < 2) ? v.x : (i < 4) ? v.y : (i < 6) ? v.z : v.w;
    __half2 h2 = *reinterpret_cast<const __half2*>(&w);
    return (i & 1) ? __high2float(h2) : __low2float(h2);
}
__device__ __forceinline__ float getf(const float4& a, const float4& b, int i) {
    const float4& v = (i < 4) ? a : b;
    int j = i & 3;
    return (j == 0) ? v.x : (j == 1) ? v.y : (j == 2) ? v.z : v.w;
}

#define HFMA2(z, w, f) asm("fma.rn.f16x2 %0, %1, %2, %0;" : "+r"(z) : "r"(w), "r"(f))
#define TANH2(d, z)    asm("tanh.approx.f16x2 %0, %1;" : "=r"(d) : "r"(z))

#define LDMATRIX_X4(r0,r1,r2,r3, addr) \
    asm volatile("ldmatrix.sync.aligned.m8n8.x4.shared.b16 {%0,%1,%2,%3}, [%4];" \
        : "=r"(r0),"=r"(r1),"=r"(r2),"=r"(r3) : "r"(addr))

#define MMA16816F16(c, a0,a1,a2,a3, b0,b1) \
    asm volatile("mma.sync.aligned.m16n8k16.row.col.f32.f16.f16.f32 " \
        "{%0,%1,%2,%3}, {%4,%5,%6,%7}, {%8,%9}, {%0,%1,%2,%3};" \
        : "+f"((c)[0]),"+f"((c)[1]),"+f"((c)[2]),"+f"((c)[3]) \
        : "r"(a0),"r"(a1),"r"(a2),"r"(a3), "r"(b0),"r"(b1))

// ---------------- kernel 1: state = xc@W_fc + b_fc ----------------
__global__ void k_state(const float* __restrict__ xc, const float* __restrict__ W_fc,
                        const float* __restrict__ b_fc, const float* __restrict__ b_kin) {
    int s = blockIdx.x, j = threadIdx.x;
    __shared__ float xcs[NG];
    if (j < NG) xcs[j] = xc[s*NG + j];
    __syncthreads();
    float acc = b_fc[j];
#pragma unroll
    for (int g = 0; g < NG; g++) acc = fmaf(xcs[g], W_fc[g*HS + j], acc);
    g_zbase[s*HS + j] = acc + b_kin[j];
    g_hg[s*HS + j]    = tanhf(acc);
}

// ---------------- kernel 2: per-site gate params + routing weights ----------------
__global__ void k_params(const float* __restrict__ W_r, const float* __restrict__ b_r,
                         const float* __restrict__ W_g, const float* __restrict__ b_g) {
    int s = blockIdx.x, tid = threadIdx.x;
    __shared__ float hgs[HS];
    __shared__ float pG[144], pR[144];
    hgs[tid] = g_hg[s*HS + tid];
    __syncthreads();
    for (int idx = tid; idx < 288; idx += 256) {
        int o = (idx < 144) ? idx : idx - 144;
        const float* W = (idx < 144) ? W_g : W_r;
        float acc = (idx < 144) ? b_g[o] : b_r[o];
#pragma unroll 8
        for (int k = 0; k < HS; k++) acc = fmaf(hgs[k], W[k*144 + o], acc);
        if (idx < 144) pG[o] = acc; else pR[o] = acc;
    }
    __syncthreads();
    if (tid < NH) {
        int h = tid, gid = s*NH + h;
        g_prm[0][gid] = sigf(pG[0*16+h]);
        g_prm[1][gid] = sigf(pG[1*16+h]);
        g_prm[2][gid] = sigf(pG[2*16+h]);
        g_prm[3][gid] = sigf(pG[3*16+h]);
        float t = sigf(pG[4*16+h]) * 10.f; g_prm[4][gid] = t*t*t;
        g_prm[5][gid] = fmaxf(pG[5*16+h], 0.f) * 0.1f;
        g_prm[6][gid] = fminf(fmaxf(pG[7*16+h]*(1.f/6.f) + 0.5f, 0.f), 1.f) * 0.5f;
        g_prm[7][gid] = fmaxf(pG[8*16+h], 0.f);
        float m = -1e30f;
#pragma unroll
        for (int i = 0; i < 16; i++) m = fmaxf(m, pG[6*16+i]);
        float sum = 0.f;
#pragma unroll
        for (int i = 0; i < 16; i++) sum += expf(pG[6*16+i] - m);
        g_prm[8][gid] = expf(pG[6*16+h] - m) / sum;
        float r[9]; float rm = -1e30f;
#pragma unroll
        for (int i = 0; i < 9; i++) { r[i] = pR[h*9 + i]; rm = fmaxf(rm, r[i]); }
        float rs = 0.f;
#pragma unroll
        for (int i = 0; i < 9; i++) { r[i] = expf(r[i] - rm); rs += r[i]; }
        float inv = 1.f / rs;
        float c = 0.f, w[8], ws = 0.f;
#pragma unroll
        for (int i = 0; i < 8; i++) {
            float si = r[i] * inv; c += si;
            float wi = fminf(c, 1.f - c + si);
            w[i] = wi; ws += wi;
        }
        float wsi = 1.f / ws;
#pragma unroll
        for (int i = 0; i < 8; i++) g_wr[gid*NR + i] = w[i] * wsi;
    }
}

// ---------------- kernel 3: K-param MLP, f16x2 phase-1 + fp16 mma, 2 CTAs/SM ----------------
__global__ void __launch_bounds__(256, 2) k_kparam(
        const float* __restrict__ x, const float* __restrict__ W_kin,
        const float* __restrict__ W_kout, const float* __restrict__ b_kout) {
    extern __shared__ char sm[];
    uint32_t smb = smem_u32(sm);
    float* ft   = (float*)(sm + OF_FT);
    uint4* wz4  = (uint4*)(sm + OF_WZ);
    uint32_t* zb2 = (uint32_t*)(sm + OF_ZB2);
    int s = blockIdx.x, tid = threadIdx.x;
    int w = tid >> 5, lane = tid & 31;

    // ---- one-time setup ----
    if (tid < 128) {
        int k = tid * 2;
        wz4[tid] = make_uint4(
            packh2(W_kin[0*HS+k], W_kin[0*HS+k+1]),
            packh2(W_kin[1*HS+k], W_kin[1*HS+k+1]),
            packh2(W_kin[2*HS+k], W_kin[2*HS+k+1]),
            packh2(W_kin[3*HS+k], W_kin[3*HS+k+1]));
        zb2[tid] = packh2(g_zbase[s*HS+k], g_zbase[s*HS+k+1]);
    }
    for (int idx = tid; idx < HS*NO; idx += 256) {
        int k = idx / NO, n = idx - k*NO;
        *(__half*)(sm + OF_W + n*STRIDE_H + k*2) = __float2half(W_kout[idx]);
    }

    int tl = tid & 127;
    int kh = (tid >> 7) * 128;
    int p0 = kh >> 1;

    uint32_t a_base = smb + OF_H + (uint32_t)(w*16 + (lane & 15))*STRIDE_H + (uint32_t)(lane >> 4)*16;
    const char* b_w = sm + OF_W + (lane >> 2)*STRIDE_H + (lane & 3)*4;

    float bias0[6], bias1[6];
#pragma unroll
    for (int nt = 0; nt < 6; nt++) {
        int c0 = nt*8 + (lane & 3)*2;
        bias0[nt] = b_kout[c0];
        bias1[nt] = b_kout[c0+1];
    }
    __syncthreads();

    for (int tile = 0; tile < NTILES; tile++) {
        int tb = tile * TILE_T;
        if (tid < TILE_T) {
            int t = tb + tid;
            if (t < NT) {
                const float* xr = x + (size_t)(t*NS + s) * 6;
                float Prcp = xr[0], Evp = xr[1], T1 = xr[2], T2 = xr[3];
                ft[tid*4+0] = T1; ft[tid*4+1] = T2;
                ft[tid*4+2] = xr[4]; ft[tid*4+3] = xr[5];
                float fl = fminf(fmaxf(T2 / (T2 - T1 + 1e-5f), 0.f), 1.f);
                g_Pl[s*NT + t] = Prcp * fl;
                g_Ps[s*NT + t] = Prcp * (1.f - fl);
                g_Ev[s*NT + t] = Evp;
            } else {
                ft[tid*4+0] = 0.f; ft[tid*4+1] = 0.f; ft[tid*4+2] = 0.f; ft[tid*4+3] = 0.f;
            }
        }
        __syncthreads();

        // phase 1: packed f16x2 z + tanh -> fp16 tile in smem
        {
            float4 fv = ((const float4*)ft)[tl];
            uint32_t f0 = packh2(fv.x, fv.x);
            uint32_t f1 = packh2(fv.y, fv.y);
            uint32_t f2 = packh2(fv.z, fv.z);
            uint32_t f3 = packh2(fv.w, fv.w);
            char* row = sm + OF_H + tl*STRIDE_H + kh*2;
#pragma unroll 4
            for (int p8 = 0; p8 < 16; p8++) {
                uint32_t hh[4];
#pragma unroll
                for (int j = 0; j < 4; j++) {
                    int p = p0 + p8*4 + j;
                    uint4 wv = wz4[p];
                    uint32_t z = zb2[p];
                    HFMA2(z, wv.x, f0);
                    HFMA2(z, wv.y, f1);
                    HFMA2(z, wv.z, f2);
                    HFMA2(z, wv.w, f3);
                    TANH2(hh[j], z);
                }
                *(uint4*)(row + p8*16) = make_uint4(hh[0], hh[1], hh[2], hh[3]);
            }
        }
        __syncthreads();

        // phase 2: single-pass fp16 mma
        float acc[6][4];
#pragma unroll
        for (int nt = 0; nt < 6; nt++) {
            acc[nt][0] = 0.f; acc[nt][1] = 0.f; acc[nt][2] = 0.f; acc[nt][3] = 0.f;
        }
#pragma unroll 4
        for (int ks = 0; ks < 16; ks++) {
            uint32_t koff = (uint32_t)ks * 32;
            uint32_t a0, a1, a2, a3;
            LDMATRIX_X4(a0, a1, a2, a3, a_base + koff);
#pragma unroll
            for (int nt = 0; nt < 6; nt++) {
                uint32_t bo = (uint32_t)(nt*8)*STRIDE_H + koff;
                uint32_t b0 = *(const uint32_t*)(b_w + bo);
                uint32_t b1 = *(const uint32_t*)(b_w + bo + 16);
                MMA16816F16(acc[nt], a0, a1, a2, a3, b0, b1);
            }
        }

        // epilogue: bias + activation -> transposed fp16 [s][c][t]
        {
            int t0 = tb + w*16 + (lane >> 2);
            int t1 = t0 + 8;
#pragma unroll
            for (int nt = 0; nt < 6; nt++) {
                int c0 = nt*8 + (lane & 3)*2;
                int grp = c0 >> 4;                // 0 km(exp), 1 ki(relu), 2 ke(exp)
                float v00 = acc[nt][0] + bias0[nt], v01 = acc[nt][1] + bias1[nt];
                float v10 = acc[nt][2] + bias0[nt], v11 = acc[nt][3] + bias1[nt];
                if (grp == 1) {
                    v00 = fmaxf(v00, 0.f); v01 = fmaxf(v01, 0.f);
                    v10 = fmaxf(v10, 0.f); v11 = fmaxf(v11, 0.f);
                } else {
                    v00 = __expf(v00); v01 = __expf(v01);
                    v10 = __expf(v10); v11 = __expf(v11);
                }
                __half* r0 = g_k3 + ((size_t)s*48 + c0)*NT;
                __half* r1 = r0 + NT;
                if (t0 < NT) { r0[t0] = __float2half(v00); r1[t0] = __float2half(v01); }
                if (t1 < NT) { r0[t1] = __float2half(v10); r1[t1] = __float2half(v11); }
            }
        }
        __syncthreads();
    }
}

// ---------------- kernel 4: fused scan, [s][c][t] streams, depth-2 k3 ring ----------------
__global__ void __launch_bounds__(128) k_scan(float* __restrict__ out) {
    int gid = blockIdx.x * blockDim.x + threadIdx.x;   // = s*NH + h
    int site = gid >> 4, h = gid & 15;
    float kp = g_prm[0][gid], ksg = g_prm[1][gid], kd = g_prm[2][gid];
    float gd = g_prm[3][gid], gl = g_prm[4][gid], qb = g_prm[5][gid];
    float gi = g_prm[6][gid], ge = g_prm[7][gid], ga = g_prm[8][gid];
    const float4* wrp = (const float4*)(g_wr + gid*NR);
    float4 wa = wrp[0], wb = wrp[1];
    float wrv[8] = {wa.x, wa.y, wa.z, wa.w, wb.x, wb.y, wb.z, wb.w};

    float A[8];
#pragma unroll
    for (int j = 0; j < 8; j++) A[j] = 0.f;
    float Sf = 0.f, Ss = 0.f, Sg = 0.f;

    const uint4* pkm = (const uint4*)(g_k3 + ((size_t)site*48 + h)*NT);
    const uint4* pki = (const uint4*)(g_k3 + ((size_t)site*48 + 16 + h)*NT);
    const uint4* pke = (const uint4*)(g_k3 + ((size_t)site*48 + 32 + h)*NT);
    const float4* pPs = (const float4*)(g_Ps + site*NT);
    const float4* pPl = (const float4*)(g_Pl + site*NT);
    const float4* pEv = (const float4*)(g_Ev + site*NT);

    // k3 ring, depth 2
    uint4 rkm[2], rki[2], rke[2];
    rkm[0] = pkm[0]; rki[0] = pki[0]; rke[0] = pke[0];
    rkm[1] = pkm[1]; rki[1] = pki[1]; rke[1] = pke[1];
    // P double buffer, depth 1
    float4 cPs0 = pPs[0], cPs1 = pPs[1];
    float4 cPl0 = pPl[0], cPl1 = pPl[1];
    float4 cEv0 = pEv[0], cEv1 = pEv[1];

    for (int blk = 0; blk < NBLK; blk++) {
        int cur = blk & 1;
        uint4 km_ = rkm[cur], ki_ = rki[cur], ke_ = rke[cur];
        if (blk + 2 < NBLK) {
            rkm[cur] = pkm[blk+2];
            rki[cur] = pki[blk+2];
            rke[cur] = pke[blk+2];
        }
        float4 Ps0 = cPs0, Ps1 = cPs1, Pl0 = cPl0, Pl1 = cPl1, Ev0 = cEv0, Ev1 = cEv1;
        if (blk + 1 < NBLK) {
            cPs0 = pPs[2*blk+2]; cPs1 = pPs[2*blk+3];
            cPl0 = pPl[2*blk+2]; cPl1 = pPl[2*blk+3];
            cEv0 = pEv[2*blk+2]; cEv1 = pEv[2*blk+3];
        }
        int tbase = blk * 8;
#pragma unroll
        for (int i = 0; i < 8; i++) {
            int tc = tbase + i;
            float kmt = geth(km_, i), kit = geth(ki_, i), ket = geth(ke_, i);
            float Pst = getf(Ps0, Ps1, i);
            float Plt = getf(Pl0, Pl1, i);
            float Evt = getf(Ev0, Ev1, i);

            Sf += Pst;
            float qf = fminf(Sf, kmt); Sf -= qf;
            float inflow = qf + Plt;
            float qd = inflow * gi;
            Ss += inflow * (1.f - gi);
            float E = fminf(fmaxf(Ss, 0.f), Evt * ket * ge); Ss -= E;
            float qi = fminf(kit, fmaxf(Ss, 0.f)); Ss -= qi;
            float qp = kp * fmaxf(Ss - gl, 0.f);
            float qsa = ksg * fminf(fmaxf(Ss, 0.f), gl);
            Ss -= qp + qsa;
            Sg += qsa * gd;
            float qg = fmaf(kd, Sg, qb); Sg *= (1.f - kd);
            float q = qp + qsa * (1.f - gd) + qg + qd + qi;

#pragma unroll
            for (int j = 0; j < 8; j++) A[j] = fmaf(q, wrv[j], A[j]);

            if (tc >= NR - 1) {
                float v = A[0] * ga;
                v += __shfl_xor_sync(0xffffffffu, v, 1);
                v += __shfl_xor_sync(0xffffffffu, v, 2);
                v += __shfl_xor_sync(0xffffffffu, v, 4);
                v += __shfl_xor_sync(0xffffffffu, v, 8);
                if (h == 0) out[(tc - (NR-1))*NS + site] = v;
            }
#pragma unroll
            for (int j = 0; j < 7; j++) A[j] = A[j+1];
            A[7] = 0.f;
        }
    }
}

// ---------------- launch ----------------
extern "C" void kernel_launch(void* const* d_in, const int* in_sizes, int n_in,
                              void* d_out, int out_size) {
    const float* x      = (const float*)d_in[0];
    const float* xc     = (const float*)d_in[1];
    const float* W_fc   = (const float*)d_in[2];
    const float* b_fc   = (const float*)d_in[3];
    const float* W_r    = (const float*)d_in[4];
    const float* b_r    = (const float*)d_in[5];
    const float* W_g    = (const float*)d_in[6];
    const float* b_g    = (const float*)d_in[7];
    const float* W_kin  = (const float*)d_in[8];
    const float* b_kin  = (const float*)d_in[9];
    const float* W_kout = (const float*)d_in[10];
    const float* b_kout = (const float*)d_in[11];
    float* out = (float*)d_out;

    k_state<<<NS, HS>>>(xc, W_fc, b_fc, b_kin);
    k_params<<<NS, 256>>>(W_r, b_r, W_g, b_g);

    cudaFuncSetAttribute(k_kparam, cudaFuncAttributeMaxDynamicSharedMemorySize, SMEM_BYTES);
    k_kparam<<<NS, 256, SMEM_BYTES>>>(x, W_kin, W_kout, b_kout);

    k_scan<<<(NS*NH)/128, 128>>>(out);
}

// round 10
// speedup vs baseline: 1.1993x; 1.1993x over previous
#include <cuda_runtime.h>
#include <cuda_bf16.h>
#include <cuda_fp16.h>
#include <cstdint>

#define NT   1000
#define NS   2048
#define NH   16
#define NR   8
#define HS   256
#define NG   32
#define NO   48
#define NSNH (NS*NH)
#define TILE_T 128
#define NTILES 8
#define NBLK (NT/8)           // 125
#define STRIDE_H 560          // bytes per 256-fp16 row (conflict-free ldmatrix/LDS)

// ---- dynamic smem byte layout (k_kparam) ----
#define OF_H   0                              // 128 x 560 = 71680
#define OF_W   (OF_H + 128*STRIDE_H)          // 71680, 48 x 560 = 26880
#define OF_FT  (OF_W + 48*STRIDE_H)           // 98560, 128 x 16
#define OF_WZ  (OF_FT + TILE_T*16)            // 100608, 128 x uint4 (packed W_kin half2 pairs)
#define OF_ZB2 (OF_WZ + 128*16)               // 102656, 128 x uint (packed zbase half2)
#define SMEM_BYTES (OF_ZB2 + 512 + 256)       // 103424 -> 2 CTAs/SM

// ---------------- device scratch ----------------
__device__ float g_zbase[NS*HS];
__device__ float g_hg[NS*HS];
__device__ float g_prm[9][NSNH];
__device__ float g_wr[NSNH*NR];
__device__ __half g_k3[(size_t)NS*48*NT];  // [s][c][t]: c 0..15 km, 16..31 ki, 32..47 ke
__device__ float g_Ps[NS*NT];              // [s][t]
__device__ float g_Pl[NS*NT];
__device__ float g_Ev[NS*NT];

__device__ __forceinline__ uint32_t smem_u32(const void* p) {
    uint32_t a;
    asm("{ .reg .u64 t; cvta.to.shared.u64 t, %1; cvt.u32.u64 %0, t; }" : "=r"(a) : "l"(p));
    return a;
}
__device__ __forceinline__ float sigf(float v) { return 1.f / (1.f + expf(-v)); }
__device__ __forceinline__ uint32_t packh2(float a, float b) {
    __half2 p = __floats2half2_rn(a, b);
    return *reinterpret_cast<uint32_t*>(&p);
}
__device__ __forceinline__ float geth(const uint4& v, int i) {
    uint32_t w = (i < 2) ? v.x : (i < 4) ? v.y : (i < 6) ? v.z : v.w;
    __half2 h2 = *reinterpret_cast<const __half2*>(&w);
    return (i & 1) ? __high2float(h2) : __low2float(h2);
}
__device__ __forceinline__ float getf(const float4& a, const float4& b, int i) {
    const float4& v = (i < 4) ? a : b;
    int j = i & 3;
    return (j == 0) ? v.x : (j == 1) ? v.y : (j == 2) ? v.z : v.w;
}

#define HFMA2(z, w, f) asm("fma.rn.f16x2 %0, %1, %2, %0;" : "+r"(z) : "r"(w), "r"(f))
#define TANH2(d, z)    asm("tanh.approx.f16x2 %0, %1;" : "=r"(d) : "r"(z))

#define LDMATRIX_X4(r0,r1,r2,r3, addr) \
    asm volatile("ldmatrix.sync.aligned.m8n8.x4.shared.b16 {%0,%1,%2,%3}, [%4];" \
        : "=r"(r0),"=r"(r1),"=r"(r2),"=r"(r3) : "r"(addr))

#define MMA16816F16(c, a0,a1,a2,a3, b0,b1) \
    asm volatile("mma.sync.aligned.m16n8k16.row.col.f32.f16.f16.f32 " \
        "{%0,%1,%2,%3}, {%4,%5,%6,%7}, {%8,%9}, {%0,%1,%2,%3};" \
        : "+f"((c)[0]),"+f"((c)[1]),"+f"((c)[2]),"+f"((c)[3]) \
        : "r"(a0),"r"(a1),"r"(a2),"r"(a3), "r"(b0),"r"(b1))

// ---------------- kernel 1: state = xc@W_fc + b_fc ----------------
__global__ void k_state(const float* __restrict__ xc, const float* __restrict__ W_fc,
                        const float* __restrict__ b_fc, const float* __restrict__ b_kin) {
    int s = blockIdx.x, j = threadIdx.x;
    __shared__ float xcs[NG];
    if (j < NG) xcs[j] = xc[s*NG + j];
    __syncthreads();
    float acc = b_fc[j];
#pragma unroll
    for (int g = 0; g < NG; g++) acc = fmaf(xcs[g], W_fc[g*HS + j], acc);
    g_zbase[s*HS + j] = acc + b_kin[j];
    g_hg[s*HS + j]    = tanhf(acc);
}

// ---------------- kernel 2: per-site gate params + routing weights ----------------
__global__ void k_params(const float* __restrict__ W_r, const float* __restrict__ b_r,
                         const float* __restrict__ W_g, const float* __restrict__ b_g) {
    int s = blockIdx.x, tid = threadIdx.x;
    __shared__ float hgs[HS];
    __shared__ float pG[144], pR[144];
    hgs[tid] = g_hg[s*HS + tid];
    __syncthreads();
    for (int idx = tid; idx < 288; idx += 256) {
        int o = (idx < 144) ? idx : idx - 144;
        const float* W = (idx < 144) ? W_g : W_r;
        float acc = (idx < 144) ? b_g[o] : b_r[o];
#pragma unroll 8
        for (int k = 0; k < HS; k++) acc = fmaf(hgs[k], W[k*144 + o], acc);
        if (idx < 144) pG[o] = acc; else pR[o] = acc;
    }
    __syncthreads();
    if (tid < NH) {
        int h = tid, gid = s*NH + h;
        g_prm[0][gid] = sigf(pG[0*16+h]);
        g_prm[1][gid] = sigf(pG[1*16+h]);
        g_prm[2][gid] = sigf(pG[2*16+h]);
        g_prm[3][gid] = sigf(pG[3*16+h]);
        float t = sigf(pG[4*16+h]) * 10.f; g_prm[4][gid] = t*t*t;
        g_prm[5][gid] = fmaxf(pG[5*16+h], 0.f) * 0.1f;
        g_prm[6][gid] = fminf(fmaxf(pG[7*16+h]*(1.f/6.f) + 0.5f, 0.f), 1.f) * 0.5f;
        g_prm[7][gid] = fmaxf(pG[8*16+h], 0.f);
        float m = -1e30f;
#pragma unroll
        for (int i = 0; i < 16; i++) m = fmaxf(m, pG[6*16+i]);
        float sum = 0.f;
#pragma unroll
        for (int i = 0; i < 16; i++) sum += expf(pG[6*16+i] - m);
        g_prm[8][gid] = expf(pG[6*16+h] - m) / sum;
        float r[9]; float rm = -1e30f;
#pragma unroll
        for (int i = 0; i < 9; i++) { r[i] = pR[h*9 + i]; rm = fmaxf(rm, r[i]); }
        float rs = 0.f;
#pragma unroll
        for (int i = 0; i < 9; i++) { r[i] = expf(r[i] - rm); rs += r[i]; }
        float inv = 1.f / rs;
        float c = 0.f, w[8], ws = 0.f;
#pragma unroll
        for (int i = 0; i < 8; i++) {
            float si = r[i] * inv; c += si;
            float wi = fminf(c, 1.f - c + si);
            w[i] = wi; ws += wi;
        }
        float wsi = 1.f / ws;
#pragma unroll
        for (int i = 0; i < 8; i++) g_wr[gid*NR + i] = w[i] * wsi;
    }
}

// ---------------- kernel 3: K-param MLP, f16x2 phase-1 + fp16 mma, 2 CTAs/SM ----------------
__global__ void __launch_bounds__(256, 2) k_kparam(
        const float* __restrict__ x, const float* __restrict__ W_kin,
        const float* __restrict__ W_kout, const float* __restrict__ b_kout) {
    extern __shared__ char sm[];
    uint32_t smb = smem_u32(sm);
    float* ft   = (float*)(sm + OF_FT);
    uint4* wz4  = (uint4*)(sm + OF_WZ);
    uint32_t* zb2 = (uint32_t*)(sm + OF_ZB2);
    int s = blockIdx.x, tid = threadIdx.x;
    int w = tid >> 5, lane = tid & 31;

    // ---- one-time setup ----
    if (tid < 128) {
        int k = tid * 2;
        wz4[tid] = make_uint4(
            packh2(W_kin[0*HS+k], W_kin[0*HS+k+1]),
            packh2(W_kin[1*HS+k], W_kin[1*HS+k+1]),
            packh2(W_kin[2*HS+k], W_kin[2*HS+k+1]),
            packh2(W_kin[3*HS+k], W_kin[3*HS+k+1]));
        zb2[tid] = packh2(g_zbase[s*HS+k], g_zbase[s*HS+k+1]);
    }
    for (int idx = tid; idx < HS*NO; idx += 256) {
        int k = idx / NO, n = idx - k*NO;
        *(__half*)(sm + OF_W + n*STRIDE_H + k*2) = __float2half(W_kout[idx]);
    }

    int tl = tid & 127;
    int kh = (tid >> 7) * 128;
    int p0 = kh >> 1;

    uint32_t a_base = smb + OF_H + (uint32_t)(w*16 + (lane & 15))*STRIDE_H + (uint32_t)(lane >> 4)*16;
    const char* b_w = sm + OF_W + (lane >> 2)*STRIDE_H + (lane & 3)*4;

    float bias0[6], bias1[6];
#pragma unroll
    for (int nt = 0; nt < 6; nt++) {
        int c0 = nt*8 + (lane & 3)*2;
        bias0[nt] = b_kout[c0];
        bias1[nt] = b_kout[c0+1];
    }
    __syncthreads();

    for (int tile = 0; tile < NTILES; tile++) {
        int tb = tile * TILE_T;
        if (tid < TILE_T) {
            int t = tb + tid;
            if (t < NT) {
                const float* xr = x + (size_t)(t*NS + s) * 6;
                float Prcp = xr[0], Evp = xr[1], T1 = xr[2], T2 = xr[3];
                ft[tid*4+0] = T1; ft[tid*4+1] = T2;
                ft[tid*4+2] = xr[4]; ft[tid*4+3] = xr[5];
                float fl = fminf(fmaxf(T2 / (T2 - T1 + 1e-5f), 0.f), 1.f);
                g_Pl[s*NT + t] = Prcp * fl;
                g_Ps[s*NT + t] = Prcp * (1.f - fl);
                g_Ev[s*NT + t] = Evp;
            } else {
                ft[tid*4+0] = 0.f; ft[tid*4+1] = 0.f; ft[tid*4+2] = 0.f; ft[tid*4+3] = 0.f;
            }
        }
        __syncthreads();

        // phase 1: packed f16x2 z + tanh -> fp16 tile in smem
        {
            float4 fv = ((const float4*)ft)[tl];
            uint32_t f0 = packh2(fv.x, fv.x);
            uint32_t f1 = packh2(fv.y, fv.y);
            uint32_t f2 = packh2(fv.z, fv.z);
            uint32_t f3 = packh2(fv.w, fv.w);
            char* row = sm + OF_H + tl*STRIDE_H + kh*2;
#pragma unroll 4
            for (int p8 = 0; p8 < 16; p8++) {
                uint32_t hh[4];
#pragma unroll
                for (int j = 0; j < 4; j++) {
                    int p = p0 + p8*4 + j;
                    uint4 wv = wz4[p];
                    uint32_t z = zb2[p];
                    HFMA2(z, wv.x, f0);
                    HFMA2(z, wv.y, f1);
                    HFMA2(z, wv.z, f2);
                    HFMA2(z, wv.w, f3);
                    TANH2(hh[j], z);
                }
                *(uint4*)(row + p8*16) = make_uint4(hh[0], hh[1], hh[2], hh[3]);
            }
        }
        __syncthreads();

        // phase 2: single-pass fp16 mma
        float acc[6][4];
#pragma unroll
        for (int nt = 0; nt < 6; nt++) {
            acc[nt][0] = 0.f; acc[nt][1] = 0.f; acc[nt][2] = 0.f; acc[nt][3] = 0.f;
        }
#pragma unroll 4
        for (int ks = 0; ks < 16; ks++) {
            uint32_t koff = (uint32_t)ks * 32;
            uint32_t a0, a1, a2, a3;
            LDMATRIX_X4(a0, a1, a2, a3, a_base + koff);
#pragma unroll
            for (int nt = 0; nt < 6; nt++) {
                uint32_t bo = (uint32_t)(nt*8)*STRIDE_H + koff;
                uint32_t b0 = *(const uint32_t*)(b_w + bo);
                uint32_t b1 = *(const uint32_t*)(b_w + bo + 16);
                MMA16816F16(acc[nt], a0, a1, a2, a3, b0, b1);
            }
        }

        // epilogue: bias + activation -> transposed fp16 [s][c][t]
        {
            int t0 = tb + w*16 + (lane >> 2);
            int t1 = t0 + 8;
#pragma unroll
            for (int nt = 0; nt < 6; nt++) {
                int c0 = nt*8 + (lane & 3)*2;
                int grp = c0 >> 4;                // 0 km(exp), 1 ki(relu), 2 ke(exp)
                float v00 = acc[nt][0] + bias0[nt], v01 = acc[nt][1] + bias1[nt];
                float v10 = acc[nt][2] + bias0[nt], v11 = acc[nt][3] + bias1[nt];
                if (grp == 1) {
                    v00 = fmaxf(v00, 0.f); v01 = fmaxf(v01, 0.f);
                    v10 = fmaxf(v10, 0.f); v11 = fmaxf(v11, 0.f);
                } else {
                    v00 = __expf(v00); v01 = __expf(v01);
                    v10 = __expf(v10); v11 = __expf(v11);
                }
                __half* r0 = g_k3 + ((size_t)s*48 + c0)*NT;
                __half* r1 = r0 + NT;
                if (t0 < NT) { r0[t0] = __float2half(v00); r1[t0] = __float2half(v01); }
                if (t1 < NT) { r0[t1] = __float2half(v10); r1[t1] = __float2half(v11); }
            }
        }
        __syncthreads();
    }
}

// ---------------- kernel 4: fused scan — R7-proven structure (named regs, depth-1 prefetch) ----------------
__global__ void __launch_bounds__(128) k_scan(float* __restrict__ out) {
    int gid = blockIdx.x * blockDim.x + threadIdx.x;   // = s*NH + h
    int site = gid >> 4, h = gid & 15;
    float kp = g_prm[0][gid], ksg = g_prm[1][gid], kd = g_prm[2][gid];
    float gd = g_prm[3][gid], gl = g_prm[4][gid], qb = g_prm[5][gid];
    float gi = g_prm[6][gid], ge = g_prm[7][gid], ga = g_prm[8][gid];
    const float4* wrp = (const float4*)(g_wr + gid*NR);
    float4 wa = wrp[0], wb = wrp[1];
    float wrv[8] = {wa.x, wa.y, wa.z, wa.w, wb.x, wb.y, wb.z, wb.w};

    float A[8];
#pragma unroll
    for (int j = 0; j < 8; j++) A[j] = 0.f;
    float Sf = 0.f, Ss = 0.f, Sg = 0.f;

    const uint4* pkm = (const uint4*)(g_k3 + ((size_t)site*48 + h)*NT);        // 8 halfs / load
    const uint4* pki = (const uint4*)(g_k3 + ((size_t)site*48 + 16 + h)*NT);
    const uint4* pke = (const uint4*)(g_k3 + ((size_t)site*48 + 32 + h)*NT);
    const float4* pPs = (const float4*)(g_Ps + site*NT);                       // 4 floats / load
    const float4* pPl = (const float4*)(g_Pl + site*NT);
    const float4* pEv = (const float4*)(g_Ev + site*NT);

    // current block buffers
    uint4 ckm = pkm[0], cki = pki[0], cke = pke[0];
    float4 cPs0 = pPs[0], cPs1 = pPs[1];
    float4 cPl0 = pPl[0], cPl1 = pPl[1];
    float4 cEv0 = pEv[0], cEv1 = pEv[1];

#pragma unroll 2
    for (int blk = 0; blk < NBLK; blk++) {
        // prefetch next block
        uint4 nkm, nki, nke;
        float4 nPs0, nPs1, nPl0, nPl1, nEv0, nEv1;
        if (blk + 1 < NBLK) {
            nkm = pkm[blk+1]; nki = pki[blk+1]; nke = pke[blk+1];
            nPs0 = pPs[2*blk+2]; nPs1 = pPs[2*blk+3];
            nPl0 = pPl[2*blk+2]; nPl1 = pPl[2*blk+3];
            nEv0 = pEv[2*blk+2]; nEv1 = pEv[2*blk+3];
        }
        int tbase = blk * 8;
#pragma unroll
        for (int i = 0; i < 8; i++) {
            int tc = tbase + i;
            float kmt = geth(ckm, i), kit = geth(cki, i), ket = geth(cke, i);
            float Pst = getf(cPs0, cPs1, i);
            float Plt = getf(cPl0, cPl1, i);
            float Evt = getf(cEv0, cEv1, i);

            Sf += Pst;
            float qf = fminf(Sf, kmt); Sf -= qf;
            float inflow = qf + Plt;
            float qd = inflow * gi;
            Ss += inflow * (1.f - gi);
            float E = fminf(fmaxf(Ss, 0.f), Evt * ket * ge); Ss -= E;
            float qi = fminf(kit, fmaxf(Ss, 0.f)); Ss -= qi;
            float qp = kp * fmaxf(Ss - gl, 0.f);
            float qsa = ksg * fminf(fmaxf(Ss, 0.f), gl);
            Ss -= qp + qsa;
            Sg += qsa * gd;
            float qg = fmaf(kd, Sg, qb); Sg *= (1.f - kd);
            float q = qp + qsa * (1.f - gd) + qg + qd + qi;

#pragma unroll
            for (int j = 0; j < 8; j++) A[j] = fmaf(q, wrv[j], A[j]);

            if (tc >= NR - 1) {
                float v = A[0] * ga;
                v += __shfl_xor_sync(0xffffffffu, v, 1);
                v += __shfl_xor_sync(0xffffffffu, v, 2);
                v += __shfl_xor_sync(0xffffffffu, v, 4);
                v += __shfl_xor_sync(0xffffffffu, v, 8);
                if (h == 0) out[(tc - (NR-1))*NS + site] = v;
            }
#pragma unroll
            for (int j = 0; j < 7; j++) A[j] = A[j+1];
            A[7] = 0.f;
        }
        if (blk + 1 < NBLK) {
            ckm = nkm; cki = nki; cke = nke;
            cPs0 = nPs0; cPs1 = nPs1;
            cPl0 = nPl0; cPl1 = nPl1;
            cEv0 = nEv0; cEv1 = nEv1;
        }
    }
}

// ---------------- launch ----------------
extern "C" void kernel_launch(void* const* d_in, const int* in_sizes, int n_in,
                              void* d_out, int out_size) {
    const float* x      = (const float*)d_in[0];
    const float* xc     = (const float*)d_in[1];
    const float* W_fc   = (const float*)d_in[2];
    const float* b_fc   = (const float*)d_in[3];
    const float* W_r    = (const float*)d_in[4];
    const float* b_r    = (const float*)d_in[5];
    const float* W_g    = (const float*)d_in[6];
    const float* b_g    = (const float*)d_in[7];
    const float* W_kin  = (const float*)d_in[8];
    const float* b_kin  = (const float*)d_in[9];
    const float* W_kout = (const float*)d_in[10];
    const float* b_kout = (const float*)d_in[11];
    float* out = (float*)d_out;

    k_state<<<NS, HS>>>(xc, W_fc, b_fc, b_kin);
    k_params<<<NS, 256>>>(W_r, b_r, W_g, b_g);

    cudaFuncSetAttribute(k_kparam, cudaFuncAttributeMaxDynamicSharedMemorySize, SMEM_BYTES);
    k_kparam<<<NS, 256, SMEM_BYTES>>>(x, W_kin, W_kout, b_kout);

    k_scan<<<(NS*NH)/128, 128>>>(out);
}

// round 11
// speedup vs baseline: 1.2075x; 1.0069x over previous
#include <cuda_runtime.h>
#include <cuda_bf16.h>
#include <cuda_fp16.h>
#include <cstdint>

#define NT   1000
#define NS   2048
#define NH   16
#define NR   8
#define HS   256
#define NG   32
#define NO   48
#define NSNH (NS*NH)
#define TILE_T 128
#define NTILES 8
#define NBLK (NT/8)           // 125
#define STRIDE_H 560          // bytes per 256-fp16 row (conflict-free ldmatrix/LDS)

// ---- dynamic smem byte layout (k_kparam) ----
#define OF_H   0                              // 128 x 560 = 71680
#define OF_W   (OF_H + 128*STRIDE_H)          // 71680, 48 x 560 = 26880
#define OF_FT  (OF_W + 48*STRIDE_H)           // 98560, 128 x 16
#define OF_WZ  (OF_FT + TILE_T*16)            // 100608, 128 x uint4 (packed W_kin half2 pairs)
#define OF_ZB2 (OF_WZ + 128*16)               // 102656, 128 x uint (packed zbase half2)
#define SMEM_BYTES (OF_ZB2 + 512 + 256)       // 103424 -> 2 CTAs/SM

// ---------------- device scratch ----------------
__device__ float g_zbase[NS*HS];
__device__ float g_hg[NS*HS];
__device__ float g_prm[9][NSNH];
__device__ float g_wr[NSNH*NR];
__device__ __half g_k3[(size_t)NS*48*NT];  // [s][c][t]: c 0..15 km, 16..31 ki, 32..47 ke
__device__ float g_Ps[NS*NT];              // [s][t]
__device__ float g_Pl[NS*NT];
__device__ float g_Ev[NS*NT];

__device__ __forceinline__ uint32_t smem_u32(const void* p) {
    uint32_t a;
    asm("{ .reg .u64 t; cvta.to.shared.u64 t, %1; cvt.u32.u64 %0, t; }" : "=r"(a) : "l"(p));
    return a;
}
__device__ __forceinline__ float sigf(float v) { return 1.f / (1.f + expf(-v)); }
__device__ __forceinline__ uint32_t packh2(float a, float b) {
    __half2 p = __floats2half2_rn(a, b);
    return *reinterpret_cast<uint32_t*>(&p);
}
__device__ __forceinline__ float geth(const uint4& v, int i) {
    uint32_t w = (i < 2) ? v.x : (i < 4) ? v.y : (i < 6) ? v.z : v.w;
    __half2 h2 = *reinterpret_cast<const __half2*>(&w);
    return (i & 1) ? __high2float(h2) : __low2float(h2);
}
__device__ __forceinline__ float getf(const float4& a, const float4& b, int i) {
    const float4& v = (i < 4) ? a : b;
    int j = i & 3;
    return (j == 0) ? v.x : (j == 1) ? v.y : (j == 2) ? v.z : v.w;
}

#define HFMA2(z, w, f) asm("fma.rn.f16x2 %0, %1, %2, %0;" : "+r"(z) : "r"(w), "r"(f))
#define TANH2(d, z)    asm("tanh.approx.f16x2 %0, %1;" : "=r"(d) : "r"(z))

#define LDMATRIX_X4(r0,r1,r2,r3, addr) \
    asm volatile("ldmatrix.sync.aligned.m8n8.x4.shared.b16 {%0,%1,%2,%3}, [%4];" \
        : "=r"(r0),"=r"(r1),"=r"(r2),"=r"(r3) : "r"(addr))

// fp16-accumulate mma: C/D are 2 packed half2 regs
#define MMA16816H(c, a0,a1,a2,a3, b0,b1) \
    asm volatile("mma.sync.aligned.m16n8k16.row.col.f16.f16.f16.f16 " \
        "{%0,%1}, {%2,%3,%4,%5}, {%6,%7}, {%0,%1};" \
        : "+r"((c)[0]),"+r"((c)[1]) \
        : "r"(a0),"r"(a1),"r"(a2),"r"(a3), "r"(b0),"r"(b1))

// ---------------- kernel 1: state = xc@W_fc + b_fc ----------------
__global__ void k_state(const float* __restrict__ xc, const float* __restrict__ W_fc,
                        const float* __restrict__ b_fc, const float* __restrict__ b_kin) {
    int s = blockIdx.x, j = threadIdx.x;
    __shared__ float xcs[NG];
    if (j < NG) xcs[j] = xc[s*NG + j];
    __syncthreads();
    float acc = b_fc[j];
#pragma unroll
    for (int g = 0; g < NG; g++) acc = fmaf(xcs[g], W_fc[g*HS + j], acc);
    g_zbase[s*HS + j] = acc + b_kin[j];
    g_hg[s*HS + j]    = tanhf(acc);
}

// ---------------- kernel 2: per-site gate params + routing weights ----------------
__global__ void k_params(const float* __restrict__ W_r, const float* __restrict__ b_r,
                         const float* __restrict__ W_g, const float* __restrict__ b_g) {
    int s = blockIdx.x, tid = threadIdx.x;
    __shared__ float hgs[HS];
    __shared__ float pG[144], pR[144];
    hgs[tid] = g_hg[s*HS + tid];
    __syncthreads();
    for (int idx = tid; idx < 288; idx += 256) {
        int o = (idx < 144) ? idx : idx - 144;
        const float* W = (idx < 144) ? W_g : W_r;
        float acc = (idx < 144) ? b_g[o] : b_r[o];
#pragma unroll 8
        for (int k = 0; k < HS; k++) acc = fmaf(hgs[k], W[k*144 + o], acc);
        if (idx < 144) pG[o] = acc; else pR[o] = acc;
    }
    __syncthreads();
    if (tid < NH) {
        int h = tid, gid = s*NH + h;
        g_prm[0][gid] = sigf(pG[0*16+h]);
        g_prm[1][gid] = sigf(pG[1*16+h]);
        g_prm[2][gid] = sigf(pG[2*16+h]);
        g_prm[3][gid] = sigf(pG[3*16+h]);
        float t = sigf(pG[4*16+h]) * 10.f; g_prm[4][gid] = t*t*t;
        g_prm[5][gid] = fmaxf(pG[5*16+h], 0.f) * 0.1f;
        g_prm[6][gid] = fminf(fmaxf(pG[7*16+h]*(1.f/6.f) + 0.5f, 0.f), 1.f) * 0.5f;
        g_prm[7][gid] = fmaxf(pG[8*16+h], 0.f);
        float m = -1e30f;
#pragma unroll
        for (int i = 0; i < 16; i++) m = fmaxf(m, pG[6*16+i]);
        float sum = 0.f;
#pragma unroll
        for (int i = 0; i < 16; i++) sum += expf(pG[6*16+i] - m);
        g_prm[8][gid] = expf(pG[6*16+h] - m) / sum;
        float r[9]; float rm = -1e30f;
#pragma unroll
        for (int i = 0; i < 9; i++) { r[i] = pR[h*9 + i]; rm = fmaxf(rm, r[i]); }
        float rs = 0.f;
#pragma unroll
        for (int i = 0; i < 9; i++) { r[i] = expf(r[i] - rm); rs += r[i]; }
        float inv = 1.f / rs;
        float c = 0.f, w[8], ws = 0.f;
#pragma unroll
        for (int i = 0; i < 8; i++) {
            float si = r[i] * inv; c += si;
            float wi = fminf(c, 1.f - c + si);
            w[i] = wi; ws += wi;
        }
        float wsi = 1.f / ws;
#pragma unroll
        for (int i = 0; i < 8; i++) g_wr[gid*NR + i] = w[i] * wsi;
    }
}

// ---------------- kernel 3: K-param MLP, f16x2 phase-1 + fp16-acc mma, 2 CTAs/SM ----------------
__global__ void __launch_bounds__(256, 2) k_kparam(
        const float* __restrict__ x, const float* __restrict__ W_kin,
        const float* __restrict__ W_kout, const float* __restrict__ b_kout) {
    extern __shared__ char sm[];
    uint32_t smb = smem_u32(sm);
    float* ft   = (float*)(sm + OF_FT);
    uint4* wz4  = (uint4*)(sm + OF_WZ);
    uint32_t* zb2 = (uint32_t*)(sm + OF_ZB2);
    int s = blockIdx.x, tid = threadIdx.x;
    int w = tid >> 5, lane = tid & 31;

    // ---- one-time setup ----
    if (tid < 128) {
        int k = tid * 2;
        wz4[tid] = make_uint4(
            packh2(W_kin[0*HS+k], W_kin[0*HS+k+1]),
            packh2(W_kin[1*HS+k], W_kin[1*HS+k+1]),
            packh2(W_kin[2*HS+k], W_kin[2*HS+k+1]),
            packh2(W_kin[3*HS+k], W_kin[3*HS+k+1]));
        zb2[tid] = packh2(g_zbase[s*HS+k], g_zbase[s*HS+k+1]);
    }
    for (int idx = tid; idx < HS*NO; idx += 256) {
        int k = idx / NO, n = idx - k*NO;
        *(__half*)(sm + OF_W + n*STRIDE_H + k*2) = __float2half(W_kout[idx]);
    }

    int tl = tid & 127;
    int kh = (tid >> 7) * 128;
    int p0 = kh >> 1;

    uint32_t a_base = smb + OF_H + (uint32_t)(w*16 + (lane & 15))*STRIDE_H + (uint32_t)(lane >> 4)*16;
    const char* b_w = sm + OF_W + (lane >> 2)*STRIDE_H + (lane & 3)*4;

    // bias packed per nt: both acc regs (t0 row, t1 row) share the same column pair
    uint32_t biasp[6];
#pragma unroll
    for (int nt = 0; nt < 6; nt++) {
        int c0 = nt*8 + (lane & 3)*2;
        biasp[nt] = packh2(b_kout[c0], b_kout[c0+1]);
    }
    __syncthreads();

    for (int tile = 0; tile < NTILES; tile++) {
        int tb = tile * TILE_T;
        if (tid < TILE_T) {
            int t = tb + tid;
            if (t < NT) {
                const float* xr = x + (size_t)(t*NS + s) * 6;
                float Prcp = xr[0], Evp = xr[1], T1 = xr[2], T2 = xr[3];
                ft[tid*4+0] = T1; ft[tid*4+1] = T2;
                ft[tid*4+2] = xr[4]; ft[tid*4+3] = xr[5];
                float fl = fminf(fmaxf(T2 / (T2 - T1 + 1e-5f), 0.f), 1.f);
                g_Pl[s*NT + t] = Prcp * fl;
                g_Ps[s*NT + t] = Prcp * (1.f - fl);
                g_Ev[s*NT + t] = Evp;
            } else {
                ft[tid*4+0] = 0.f; ft[tid*4+1] = 0.f; ft[tid*4+2] = 0.f; ft[tid*4+3] = 0.f;
            }
        }
        __syncthreads();

        // phase 1: packed f16x2 z + tanh -> fp16 tile in smem
        {
            float4 fv = ((const float4*)ft)[tl];
            uint32_t f0 = packh2(fv.x, fv.x);
            uint32_t f1 = packh2(fv.y, fv.y);
            uint32_t f2 = packh2(fv.z, fv.z);
            uint32_t f3 = packh2(fv.w, fv.w);
            char* row = sm + OF_H + tl*STRIDE_H + kh*2;
#pragma unroll 4
            for (int p8 = 0; p8 < 16; p8++) {
                uint32_t hh[4];
#pragma unroll
                for (int j = 0; j < 4; j++) {
                    int p = p0 + p8*4 + j;
                    uint4 wv = wz4[p];
                    uint32_t z = zb2[p];
                    HFMA2(z, wv.x, f0);
                    HFMA2(z, wv.y, f1);
                    HFMA2(z, wv.z, f2);
                    HFMA2(z, wv.w, f3);
                    TANH2(hh[j], z);
                }
                *(uint4*)(row + p8*16) = make_uint4(hh[0], hh[1], hh[2], hh[3]);
            }
        }
        __syncthreads();

        // phase 2: fp16-accumulate mma, bias folded into acc init
        uint32_t acc[6][2];
#pragma unroll
        for (int nt = 0; nt < 6; nt++) { acc[nt][0] = biasp[nt]; acc[nt][1] = biasp[nt]; }
#pragma unroll 4
        for (int ks = 0; ks < 16; ks++) {
            uint32_t koff = (uint32_t)ks * 32;
            uint32_t a0, a1, a2, a3;
            LDMATRIX_X4(a0, a1, a2, a3, a_base + koff);
#pragma unroll
            for (int nt = 0; nt < 6; nt++) {
                uint32_t bo = (uint32_t)(nt*8)*STRIDE_H + koff;
                uint32_t b0 = *(const uint32_t*)(b_w + bo);
                uint32_t b1 = *(const uint32_t*)(b_w + bo + 16);
                MMA16816H(acc[nt], a0, a1, a2, a3, b0, b1);
            }
        }

        // epilogue: activation -> transposed fp16 [s][c][t]
        {
            int t0 = tb + w*16 + (lane >> 2);
            int t1 = t0 + 8;
#pragma unroll
            for (int nt = 0; nt < 6; nt++) {
                int c0 = nt*8 + (lane & 3)*2;
                int grp = c0 >> 4;                // 0 km(exp), 1 ki(relu), 2 ke(exp)
                __half2 p0h = *reinterpret_cast<__half2*>(&acc[nt][0]);
                __half2 p1h = *reinterpret_cast<__half2*>(&acc[nt][1]);
                float v00 = __low2float(p0h), v01 = __high2float(p0h);
                float v10 = __low2float(p1h), v11 = __high2float(p1h);
                if (grp == 1) {
                    v00 = fmaxf(v00, 0.f); v01 = fmaxf(v01, 0.f);
                    v10 = fmaxf(v10, 0.f); v11 = fmaxf(v11, 0.f);
                } else {
                    v00 = __expf(v00); v01 = __expf(v01);
                    v10 = __expf(v10); v11 = __expf(v11);
                }
                __half* r0 = g_k3 + ((size_t)s*48 + c0)*NT;
                __half* r1 = r0 + NT;
                if (t0 < NT) { r0[t0] = __float2half(v00); r1[t0] = __float2half(v01); }
                if (t1 < NT) { r0[t1] = __float2half(v10); r1[t1] = __float2half(v11); }
            }
        }
        __syncthreads();
    }
}

// ---------------- kernel 4: fused scan — R10-proven structure, 64-thread blocks ----------------
__global__ void __launch_bounds__(64) k_scan(float* __restrict__ out) {
    int gid = blockIdx.x * blockDim.x + threadIdx.x;   // = s*NH + h
    int site = gid >> 4, h = gid & 15;
    float kp = g_prm[0][gid], ksg = g_prm[1][gid], kd = g_prm[2][gid];
    float gd = g_prm[3][gid], gl = g_prm[4][gid], qb = g_prm[5][gid];
    float gi = g_prm[6][gid], ge = g_prm[7][gid], ga = g_prm[8][gid];
    const float4* wrp = (const float4*)(g_wr + gid*NR);
    float4 wa = wrp[0], wb = wrp[1];
    float wrv[8] = {wa.x, wa.y, wa.z, wa.w, wb.x, wb.y, wb.z, wb.w};

    float A[8];
#pragma unroll
    for (int j = 0; j < 8; j++) A[j] = 0.f;
    float Sf = 0.f, Ss = 0.f, Sg = 0.f;

    const uint4* pkm = (const uint4*)(g_k3 + ((size_t)site*48 + h)*NT);        // 8 halfs / load
    const uint4* pki = (const uint4*)(g_k3 + ((size_t)site*48 + 16 + h)*NT);
    const uint4* pke = (const uint4*)(g_k3 + ((size_t)site*48 + 32 + h)*NT);
    const float4* pPs = (const float4*)(g_Ps + site*NT);                       // 4 floats / load
    const float4* pPl = (const float4*)(g_Pl + site*NT);
    const float4* pEv = (const float4*)(g_Ev + site*NT);

    // current block buffers
    uint4 ckm = pkm[0], cki = pki[0], cke = pke[0];
    float4 cPs0 = pPs[0], cPs1 = pPs[1];
    float4 cPl0 = pPl[0], cPl1 = pPl[1];
    float4 cEv0 = pEv[0], cEv1 = pEv[1];

#pragma unroll 2
    for (int blk = 0; blk < NBLK; blk++) {
        // prefetch next block
        uint4 nkm, nki, nke;
        float4 nPs0, nPs1, nPl0, nPl1, nEv0, nEv1;
        if (blk + 1 < NBLK) {
            nkm = pkm[blk+1]; nki = pki[blk+1]; nke = pke[blk+1];
            nPs0 = pPs[2*blk+2]; nPs1 = pPs[2*blk+3];
            nPl0 = pPl[2*blk+2]; nPl1 = pPl[2*blk+3];
            nEv0 = pEv[2*blk+2]; nEv1 = pEv[2*blk+3];
        }
        int tbase = blk * 8;
#pragma unroll
        for (int i = 0; i < 8; i++) {
            int tc = tbase + i;
            float kmt = geth(ckm, i), kit = geth(cki, i), ket = geth(cke, i);
            float Pst = getf(cPs0, cPs1, i);
            float Plt = getf(cPl0, cPl1, i);
            float Evt = getf(cEv0, cEv1, i);

            Sf += Pst;
            float qf = fminf(Sf, kmt); Sf -= qf;
            float inflow = qf + Plt;
            float qd = inflow * gi;
            Ss += inflow * (1.f - gi);
            float E = fminf(fmaxf(Ss, 0.f), Evt * ket * ge); Ss -= E;
            float qi = fminf(kit, fmaxf(Ss, 0.f)); Ss -= qi;
            float qp = kp * fmaxf(Ss - gl, 0.f);
            float qsa = ksg * fminf(fmaxf(Ss, 0.f), gl);
            Ss -= qp + qsa;
            Sg += qsa * gd;
            float qg = fmaf(kd, Sg, qb); Sg *= (1.f - kd);
            float q = qp + qsa * (1.f - gd) + qg + qd + qi;

#pragma unroll
            for (int j = 0; j < 8; j++) A[j] = fmaf(q, wrv[j], A[j]);

            if (tc >= NR - 1) {
                float v = A[0] * ga;
                v += __shfl_xor_sync(0xffffffffu, v, 1);
                v += __shfl_xor_sync(0xffffffffu, v, 2);
                v += __shfl_xor_sync(0xffffffffu, v, 4);
                v += __shfl_xor_sync(0xffffffffu, v, 8);
                if (h == 0) out[(tc - (NR-1))*NS + site] = v;
            }
#pragma unroll
            for (int j = 0; j < 7; j++) A[j] = A[j+1];
            A[7] = 0.f;
        }
        if (blk + 1 < NBLK) {
            ckm = nkm; cki = nki; cke = nke;
            cPs0 = nPs0; cPs1 = nPs1;
            cPl0 = nPl0; cPl1 = nPl1;
            cEv0 = nEv0; cEv1 = nEv1;
        }
    }
}

// ---------------- launch ----------------
extern "C" void kernel_launch(void* const* d_in, const int* in_sizes, int n_in,
                              void* d_out, int out_size) {
    const float* x      = (const float*)d_in[0];
    const float* xc     = (const float*)d_in[1];
    const float* W_fc   = (const float*)d_in[2];
    const float* b_fc   = (const float*)d_in[3];
    const float* W_r    = (const float*)d_in[4];
    const float* b_r    = (const float*)d_in[5];
    const float* W_g    = (const float*)d_in[6];
    const float* b_g    = (const float*)d_in[7];
    const float* W_kin  = (const float*)d_in[8];
    const float* b_kin  = (const float*)d_in[9];
    const float* W_kout = (const float*)d_in[10];
    const float* b_kout = (const float*)d_in[11];
    float* out = (float*)d_out;

    k_state<<<NS, HS>>>(xc, W_fc, b_fc, b_kin);
    k_params<<<NS, 256>>>(W_r, b_r, W_g, b_g);

    cudaFuncSetAttribute(k_kparam, cudaFuncAttributeMaxDynamicSharedMemorySize, SMEM_BYTES);
    k_kparam<<<NS, 256, SMEM_BYTES>>>(x, W_kin, W_kout, b_kout);

    k_scan<<<(NS*NH)/64, 64>>>(out);
}

// round 12
// speedup vs baseline: 1.2722x; 1.0536x over previous
#include <cuda_runtime.h>
#include <cuda_bf16.h>
#include <cuda_fp16.h>
#include <cstdint>

#define NT   1000
#define NS   2048
#define NH   16
#define NR   8
#define HS   256
#define NG   32
#define NO   48
#define NSNH (NS*NH)
#define TILE_T 128
#define NTILES 8
#define NBLK (NT/8)           // 125
#define STRIDE_H 560          // bytes per 256-fp16 row (conflict-free ldmatrix/LDS)

// ---- dynamic smem byte layout (k_kparam) ----
#define OF_H   0                              // 128 x 560 = 71680
#define OF_W   (OF_H + 128*STRIDE_H)          // 71680, 48 x 560 = 26880
#define OF_FT  (OF_W + 48*STRIDE_H)           // 98560, 128 x 16
#define OF_WZ  (OF_FT + TILE_T*16)            // 100608, 128 x uint4 (packed W_kin half2 pairs)
#define OF_ZB2 (OF_WZ + 128*16)               // 102656, 128 x uint (packed zbase half2)
#define SMEM_BYTES (OF_ZB2 + 512 + 256)       // 103424 -> 2 CTAs/SM

// ---------------- device scratch ----------------
__device__ float g_zbase[NS*HS];
__device__ float g_hg[NS*HS];
__device__ float g_prm[9][NSNH];
__device__ float g_wr[NSNH*NR];
__device__ __half g_k3[(size_t)NS*48*NT];  // [s][c][t]: c 0..15 km, 16..31 ki, 32..47 ke
__device__ float g_Ps[NS*NT];              // [s][t]
__device__ float g_Pl[NS*NT];
__device__ float g_Ev[NS*NT];

__device__ __forceinline__ uint32_t smem_u32(const void* p) {
    uint32_t a;
    asm("{ .reg .u64 t; cvta.to.shared.u64 t, %1; cvt.u32.u64 %0, t; }" : "=r"(a) : "l"(p));
    return a;
}
__device__ __forceinline__ float sigf(float v) { return 1.f / (1.f + expf(-v)); }
__device__ __forceinline__ uint32_t packh2(float a, float b) {
    __half2 p = __floats2half2_rn(a, b);
    return *reinterpret_cast<uint32_t*>(&p);
}
__device__ __forceinline__ float geth(const uint4& v, int i) {
    uint32_t w = (i < 2) ? v.x : (i < 4) ? v.y : (i < 6) ? v.z : v.w;
    __half2 h2 = *reinterpret_cast<const __half2*>(&w);
    return (i & 1) ? __high2float(h2) : __low2float(h2);
}
__device__ __forceinline__ float getf(const float4& a, const float4& b, int i) {
    const float4& v = (i < 4) ? a : b;
    int j = i & 3;
    return (j == 0) ? v.x : (j == 1) ? v.y : (j == 2) ? v.z : v.w;
}

#define HFMA2(z, w, f) asm("fma.rn.f16x2 %0, %1, %2, %0;" : "+r"(z) : "r"(w), "r"(f))
#define TANH2(d, z)    asm("tanh.approx.f16x2 %0, %1;" : "=r"(d) : "r"(z))

#define LDMATRIX_X4(r0,r1,r2,r3, addr) \
    asm volatile("ldmatrix.sync.aligned.m8n8.x4.shared.b16 {%0,%1,%2,%3}, [%4];" \
        : "=r"(r0),"=r"(r1),"=r"(r2),"=r"(r3) : "r"(addr))

#define LDMATRIX_X2(r0,r1, addr) \
    asm volatile("ldmatrix.sync.aligned.m8n8.x2.shared.b16 {%0,%1}, [%2];" \
        : "=r"(r0),"=r"(r1) : "r"(addr))

// fp16-accumulate mma: C/D are 2 packed half2 regs
#define MMA16816H(c, a0,a1,a2,a3, b0,b1) \
    asm volatile("mma.sync.aligned.m16n8k16.row.col.f16.f16.f16.f16 " \
        "{%0,%1}, {%2,%3,%4,%5}, {%6,%7}, {%0,%1};" \
        : "+r"((c)[0]),"+r"((c)[1]) \
        : "r"(a0),"r"(a1),"r"(a2),"r"(a3), "r"(b0),"r"(b1))

// ---------------- kernel 1: state = xc@W_fc + b_fc ----------------
__global__ void k_state(const float* __restrict__ xc, const float* __restrict__ W_fc,
                        const float* __restrict__ b_fc, const float* __restrict__ b_kin) {
    int s = blockIdx.x, j = threadIdx.x;
    __shared__ float xcs[NG];
    if (j < NG) xcs[j] = xc[s*NG + j];
    __syncthreads();
    float acc = b_fc[j];
#pragma unroll
    for (int g = 0; g < NG; g++) acc = fmaf(xcs[g], W_fc[g*HS + j], acc);
    g_zbase[s*HS + j] = acc + b_kin[j];
    g_hg[s*HS + j]    = tanhf(acc);
}

// ---------------- kernel 2: per-site gate params + routing weights ----------------
__global__ void k_params(const float* __restrict__ W_r, const float* __restrict__ b_r,
                         const float* __restrict__ W_g, const float* __restrict__ b_g) {
    int s = blockIdx.x, tid = threadIdx.x;
    __shared__ float hgs[HS];
    __shared__ float pG[144], pR[144];
    hgs[tid] = g_hg[s*HS + tid];
    __syncthreads();
    for (int idx = tid; idx < 288; idx += 256) {
        int o = (idx < 144) ? idx : idx - 144;
        const float* W = (idx < 144) ? W_g : W_r;
        float acc = (idx < 144) ? b_g[o] : b_r[o];
#pragma unroll 8
        for (int k = 0; k < HS; k++) acc = fmaf(hgs[k], W[k*144 + o], acc);
        if (idx < 144) pG[o] = acc; else pR[o] = acc;
    }
    __syncthreads();
    if (tid < NH) {
        int h = tid, gid = s*NH + h;
        g_prm[0][gid] = sigf(pG[0*16+h]);
        g_prm[1][gid] = sigf(pG[1*16+h]);
        g_prm[2][gid] = sigf(pG[2*16+h]);
        g_prm[3][gid] = sigf(pG[3*16+h]);
        float t = sigf(pG[4*16+h]) * 10.f; g_prm[4][gid] = t*t*t;
        g_prm[5][gid] = fmaxf(pG[5*16+h], 0.f) * 0.1f;
        g_prm[6][gid] = fminf(fmaxf(pG[7*16+h]*(1.f/6.f) + 0.5f, 0.f), 1.f) * 0.5f;
        g_prm[7][gid] = fmaxf(pG[8*16+h], 0.f);
        float m = -1e30f;
#pragma unroll
        for (int i = 0; i < 16; i++) m = fmaxf(m, pG[6*16+i]);
        float sum = 0.f;
#pragma unroll
        for (int i = 0; i < 16; i++) sum += expf(pG[6*16+i] - m);
        g_prm[8][gid] = expf(pG[6*16+h] - m) / sum;
        float r[9]; float rm = -1e30f;
#pragma unroll
        for (int i = 0; i < 9; i++) { r[i] = pR[h*9 + i]; rm = fmaxf(rm, r[i]); }
        float rs = 0.f;
#pragma unroll
        for (int i = 0; i < 9; i++) { r[i] = expf(r[i] - rm); rs += r[i]; }
        float inv = 1.f / rs;
        float c = 0.f, w[8], ws = 0.f;
#pragma unroll
        for (int i = 0; i < 8; i++) {
            float si = r[i] * inv; c += si;
            float wi = fminf(c, 1.f - c + si);
            w[i] = wi; ws += wi;
        }
        float wsi = 1.f / ws;
#pragma unroll
        for (int i = 0; i < 8; i++) g_wr[gid*NR + i] = w[i] * wsi;
    }
}

// ---------------- kernel 3: K-param MLP — 4 mma warps x 2 m-tiles, ldmatrix B ----------------
__global__ void __launch_bounds__(256, 2) k_kparam(
        const float* __restrict__ x, const float* __restrict__ W_kin,
        const float* __restrict__ W_kout, const float* __restrict__ b_kout) {
    extern __shared__ char sm[];
    uint32_t smb = smem_u32(sm);
    float* ft   = (float*)(sm + OF_FT);
    uint4* wz4  = (uint4*)(sm + OF_WZ);
    uint32_t* zb2 = (uint32_t*)(sm + OF_ZB2);
    int s = blockIdx.x, tid = threadIdx.x;
    int w = tid >> 5, lane = tid & 31;

    // ---- one-time setup ----
    if (tid < 128) {
        int k = tid * 2;
        wz4[tid] = make_uint4(
            packh2(W_kin[0*HS+k], W_kin[0*HS+k+1]),
            packh2(W_kin[1*HS+k], W_kin[1*HS+k+1]),
            packh2(W_kin[2*HS+k], W_kin[2*HS+k+1]),
            packh2(W_kin[3*HS+k], W_kin[3*HS+k+1]));
        zb2[tid] = packh2(g_zbase[s*HS+k], g_zbase[s*HS+k+1]);
    }
    for (int idx = tid; idx < HS*NO; idx += 256) {
        int k = idx / NO, n = idx - k*NO;
        *(__half*)(sm + OF_W + n*STRIDE_H + k*2) = __float2half(W_kout[idx]);
    }

    int tl = tid & 127;
    int kh = (tid >> 7) * 128;
    int p0 = kh >> 1;

    // phase-2 identity (warps 0..3): two m-tiles, rows w*16 and w*16+64
    uint32_t aA = smb + OF_H + (uint32_t)(w*16 + (lane & 15))*STRIDE_H + (uint32_t)(lane >> 4)*16;
    uint32_t aB = aA + 64u*STRIDE_H;
    // B ldmatrix addresses (lanes 0..15 meaningful): row (l&7) of nt-block, +16B for tile1
    int l4 = lane & 15;
    uint32_t bm_base = smb + OF_W + (uint32_t)(l4 & 7)*STRIDE_H + (uint32_t)(l4 >> 3)*16;

    uint32_t biasp[6];
#pragma unroll
    for (int nt = 0; nt < 6; nt++) {
        int c0 = nt*8 + (lane & 3)*2;
        biasp[nt] = packh2(b_kout[c0], b_kout[c0+1]);
    }
    __syncthreads();

    for (int tile = 0; tile < NTILES; tile++) {
        int tb = tile * TILE_T;
        if (tid < TILE_T) {
            int t = tb + tid;
            if (t < NT) {
                const float* xr = x + (size_t)(t*NS + s) * 6;
                float Prcp = xr[0], Evp = xr[1], T1 = xr[2], T2 = xr[3];
                ft[tid*4+0] = T1; ft[tid*4+1] = T2;
                ft[tid*4+2] = xr[4]; ft[tid*4+3] = xr[5];
                float fl = fminf(fmaxf(T2 / (T2 - T1 + 1e-5f), 0.f), 1.f);
                g_Pl[s*NT + t] = Prcp * fl;
                g_Ps[s*NT + t] = Prcp * (1.f - fl);
                g_Ev[s*NT + t] = Evp;
            } else {
                ft[tid*4+0] = 0.f; ft[tid*4+1] = 0.f; ft[tid*4+2] = 0.f; ft[tid*4+3] = 0.f;
            }
        }
        __syncthreads();

        // phase 1: packed f16x2 z + tanh -> fp16 tile in smem (all 8 warps)
        {
            float4 fv = ((const float4*)ft)[tl];
            uint32_t f0 = packh2(fv.x, fv.x);
            uint32_t f1 = packh2(fv.y, fv.y);
            uint32_t f2 = packh2(fv.z, fv.z);
            uint32_t f3 = packh2(fv.w, fv.w);
            char* row = sm + OF_H + tl*STRIDE_H + kh*2;
#pragma unroll 4
            for (int p8 = 0; p8 < 16; p8++) {
                uint32_t hh[4];
#pragma unroll
                for (int j = 0; j < 4; j++) {
                    int p = p0 + p8*4 + j;
                    uint4 wv = wz4[p];
                    uint32_t z = zb2[p];
                    HFMA2(z, wv.x, f0);
                    HFMA2(z, wv.y, f1);
                    HFMA2(z, wv.z, f2);
                    HFMA2(z, wv.w, f3);
                    TANH2(hh[j], z);
                }
                *(uint4*)(row + p8*16) = make_uint4(hh[0], hh[1], hh[2], hh[3]);
            }
        }
        __syncthreads();

        // phase 2: warps 0..3 — fp16-acc mma, 2 m-tiles per warp, B shared via ldmatrix
        if (w < 4) {
            uint32_t acc[2][6][2];
#pragma unroll
            for (int nt = 0; nt < 6; nt++) {
                acc[0][nt][0] = biasp[nt]; acc[0][nt][1] = biasp[nt];
                acc[1][nt][0] = biasp[nt]; acc[1][nt][1] = biasp[nt];
            }
#pragma unroll 4
            for (int ks = 0; ks < 16; ks++) {
                uint32_t koff = (uint32_t)ks * 32;
                uint32_t x0, x1, x2, x3, y0, y1, y2, y3;
                LDMATRIX_X4(x0, x1, x2, x3, aA + koff);
                LDMATRIX_X4(y0, y1, y2, y3, aB + koff);
#pragma unroll
                for (int nt = 0; nt < 6; nt++) {
                    uint32_t b0, b1;
                    LDMATRIX_X2(b0, b1, bm_base + (uint32_t)(nt*8)*STRIDE_H + koff);
                    MMA16816H(acc[0][nt], x0, x1, x2, x3, b0, b1);
                    MMA16816H(acc[1][nt], y0, y1, y2, y3, b0, b1);
                }
            }

            // epilogue: both m-tiles
#pragma unroll
            for (int half = 0; half < 2; half++) {
                int t0 = tb + w*16 + half*64 + (lane >> 2);
                int t1 = t0 + 8;
#pragma unroll
                for (int nt = 0; nt < 6; nt++) {
                    int c0 = nt*8 + (lane & 3)*2;
                    int grp = c0 >> 4;            // 0 km(exp), 1 ki(relu), 2 ke(exp)
                    __half2 p0h = *reinterpret_cast<__half2*>(&acc[half][nt][0]);
                    __half2 p1h = *reinterpret_cast<__half2*>(&acc[half][nt][1]);
                    float v00 = __low2float(p0h), v01 = __high2float(p0h);
                    float v10 = __low2float(p1h), v11 = __high2float(p1h);
                    if (grp == 1) {
                        v00 = fmaxf(v00, 0.f); v01 = fmaxf(v01, 0.f);
                        v10 = fmaxf(v10, 0.f); v11 = fmaxf(v11, 0.f);
                    } else {
                        v00 = __expf(v00); v01 = __expf(v01);
                        v10 = __expf(v10); v11 = __expf(v11);
                    }
                    __half* r0 = g_k3 + ((size_t)s*48 + c0)*NT;
                    __half* r1 = r0 + NT;
                    if (t0 < NT) { r0[t0] = __float2half(v00); r1[t0] = __float2half(v01); }
                    if (t1 < NT) { r0[t1] = __float2half(v10); r1[t1] = __float2half(v11); }
                }
            }
        }
        __syncthreads();
    }
}

// ---------------- kernel 4: fused scan — R10-proven structure, 64-thread blocks ----------------
__global__ void __launch_bounds__(64) k_scan(float* __restrict__ out) {
    int gid = blockIdx.x * blockDim.x + threadIdx.x;   // = s*NH + h
    int site = gid >> 4, h = gid & 15;
    float kp = g_prm[0][gid], ksg = g_prm[1][gid], kd = g_prm[2][gid];
    float gd = g_prm[3][gid], gl = g_prm[4][gid], qb = g_prm[5][gid];
    float gi = g_prm[6][gid], ge = g_prm[7][gid], ga = g_prm[8][gid];
    const float4* wrp = (const float4*)(g_wr + gid*NR);
    float4 wa = wrp[0], wb = wrp[1];
    float wrv[8] = {wa.x, wa.y, wa.z, wa.w, wb.x, wb.y, wb.z, wb.w};

    float A[8];
#pragma unroll
    for (int j = 0; j < 8; j++) A[j] = 0.f;
    float Sf = 0.f, Ss = 0.f, Sg = 0.f;

    const uint4* pkm = (const uint4*)(g_k3 + ((size_t)site*48 + h)*NT);
    const uint4* pki = (const uint4*)(g_k3 + ((size_t)site*48 + 16 + h)*NT);
    const uint4* pke = (const uint4*)(g_k3 + ((size_t)site*48 + 32 + h)*NT);
    const float4* pPs = (const float4*)(g_Ps + site*NT);
    const float4* pPl = (const float4*)(g_Pl + site*NT);
    const float4* pEv = (const float4*)(g_Ev + site*NT);

    uint4 ckm = pkm[0], cki = pki[0], cke = pke[0];
    float4 cPs0 = pPs[0], cPs1 = pPs[1];
    float4 cPl0 = pPl[0], cPl1 = pPl[1];
    float4 cEv0 = pEv[0], cEv1 = pEv[1];

#pragma unroll 2
    for (int blk = 0; blk < NBLK; blk++) {
        uint4 nkm, nki, nke;
        float4 nPs0, nPs1, nPl0, nPl1, nEv0, nEv1;
        if (blk + 1 < NBLK) {
            nkm = pkm[blk+1]; nki = pki[blk+1]; nke = pke[blk+1];
            nPs0 = pPs[2*blk+2]; nPs1 = pPs[2*blk+3];
            nPl0 = pPl[2*blk+2]; nPl1 = pPl[2*blk+3];
            nEv0 = pEv[2*blk+2]; nEv1 = pEv[2*blk+3];
        }
        int tbase = blk * 8;
#pragma unroll
        for (int i = 0; i < 8; i++) {
            int tc = tbase + i;
            float kmt = geth(ckm, i), kit = geth(cki, i), ket = geth(cke, i);
            float Pst = getf(cPs0, cPs1, i);
            float Plt = getf(cPl0, cPl1, i);
            float Evt = getf(cEv0, cEv1, i);

            Sf += Pst;
            float qf = fminf(Sf, kmt); Sf -= qf;
            float inflow = qf + Plt;
            float qd = inflow * gi;
            Ss += inflow * (1.f - gi);
            float E = fminf(fmaxf(Ss, 0.f), Evt * ket * ge); Ss -= E;
            float qi = fminf(kit, fmaxf(Ss, 0.f)); Ss -= qi;
            float qp = kp * fmaxf(Ss - gl, 0.f);
            float qsa = ksg * fminf(fmaxf(Ss, 0.f), gl);
            Ss -= qp + qsa;
            Sg += qsa * gd;
            float qg = fmaf(kd, Sg, qb); Sg *= (1.f - kd);
            float q = qp + qsa * (1.f - gd) + qg + qd + qi;

#pragma unroll
            for (int j = 0; j < 8; j++) A[j] = fmaf(q, wrv[j], A[j]);

            if (tc >= NR - 1) {
                float v = A[0] * ga;
                v += __shfl_xor_sync(0xffffffffu, v, 1);
                v += __shfl_xor_sync(0xffffffffu, v, 2);
                v += __shfl_xor_sync(0xffffffffu, v, 4);
                v += __shfl_xor_sync(0xffffffffu, v, 8);
                if (h == 0) out[(tc - (NR-1))*NS + site] = v;
            }
#pragma unroll
            for (int j = 0; j < 7; j++) A[j] = A[j+1];
            A[7] = 0.f;
        }
        if (blk + 1 < NBLK) {
            ckm = nkm; cki = nki; cke = nke;
            cPs0 = nPs0; cPs1 = nPs1;
            cPl0 = nPl0; cPl1 = nPl1;
            cEv0 = nEv0; cEv1 = nEv1;
        }
    }
}

// ---------------- launch ----------------
extern "C" void kernel_launch(void* const* d_in, const int* in_sizes, int n_in,
                              void* d_out, int out_size) {
    const float* x      = (const float*)d_in[0];
    const float* xc     = (const float*)d_in[1];
    const float* W_fc   = (const float*)d_in[2];
    const float* b_fc   = (const float*)d_in[3];
    const float* W_r    = (const float*)d_in[4];
    const float* b_r    = (const float*)d_in[5];
    const float* W_g    = (const float*)d_in[6];
    const float* b_g    = (const float*)d_in[7];
    const float* W_kin  = (const float*)d_in[8];
    const float* b_kin  = (const float*)d_in[9];
    const float* W_kout = (const float*)d_in[10];
    const float* b_kout = (const float*)d_in[11];
    float* out = (float*)d_out;

    k_state<<<NS, HS>>>(xc, W_fc, b_fc, b_kin);
    k_params<<<NS, 256>>>(W_r, b_r, W_g, b_g);

    cudaFuncSetAttribute(k_kparam, cudaFuncAttributeMaxDynamicSharedMemorySize, SMEM_BYTES);
    k_kparam<<<NS, 256, SMEM_BYTES>>>(x, W_kin, W_kout, b_kout);

    k_scan<<<(NS*NH)/64, 64>>>(out);
}

// round 13
// speedup vs baseline: 1.5538x; 1.2214x over previous
#include <cuda_runtime.h>
#include <cuda_bf16.h>
#include <cuda_fp16.h>
#include <cstdint>

#define NT   1000
#define NS   2048
#define NH   16
#define NR   8
#define HS   256
#define NG   32
#define NO   48
#define NSNH (NS*NH)
#define TILE_T 128
#define NTILES 8
#define NBLK (NT/8)           // 125
#define STRIDE_H 560          // bytes per 256-fp16 row (conflict-free ldmatrix)

// ---- dynamic smem byte layout (k_kparam) ----
#define OF_W   0                              // 48 x 560 = 26880
#define OF_WZ  26880                          // 128 x uint4 (packed W_kin half2 pairs)
#define OF_ZB2 (OF_WZ + 128*16)               // 28928, 128 x uint (packed zbase half2)
#define SMEM_BYTES (OF_ZB2 + 512 + 128)       // 29568 -> 4+ CTAs/SM

// ---------------- device scratch ----------------
__device__ float g_zbase[NS*HS];
__device__ float g_hg[NS*HS];
__device__ float g_prm[9][NSNH];
__device__ float g_wr[NSNH*NR];
__device__ __half g_k3[(size_t)NS*48*NT];  // [s][c][t]: c 0..15 km, 16..31 ki, 32..47 ke
__device__ float g_Ps[NS*NT];              // [s][t]
__device__ float g_Pl[NS*NT];
__device__ float g_Ev[NS*NT];

__device__ __forceinline__ uint32_t smem_u32(const void* p) {
    uint32_t a;
    asm("{ .reg .u64 t; cvta.to.shared.u64 t, %1; cvt.u32.u64 %0, t; }" : "=r"(a) : "l"(p));
    return a;
}
__device__ __forceinline__ float sigf(float v) { return 1.f / (1.f + expf(-v)); }
__device__ __forceinline__ uint32_t packh2(float a, float b) {
    __half2 p = __floats2half2_rn(a, b);
    return *reinterpret_cast<uint32_t*>(&p);
}
__device__ __forceinline__ float geth(const uint4& v, int i) {
    uint32_t w = (i < 2) ? v.x : (i < 4) ? v.y : (i < 6) ? v.z : v.w;
    __half2 h2 = *reinterpret_cast<const __half2*>(&w);
    return (i & 1) ? __high2float(h2) : __low2float(h2);
}
__device__ __forceinline__ float getf(const float4& a, const float4& b, int i) {
    const float4& v = (i < 4) ? a : b;
    int j = i & 3;
    return (j == 0) ? v.x : (j == 1) ? v.y : (j == 2) ? v.z : v.w;
}

#define HFMA2(z, w, f) asm("fma.rn.f16x2 %0, %1, %2, %0;" : "+r"(z) : "r"(w), "r"(f))
#define TANH2(d, z)    asm("tanh.approx.f16x2 %0, %1;" : "=r"(d) : "r"(z))

#define LDMATRIX_X2(r0,r1, addr) \
    asm volatile("ldmatrix.sync.aligned.m8n8.x2.shared.b16 {%0,%1}, [%2];" \
        : "=r"(r0),"=r"(r1) : "r"(addr))

// fp16-accumulate mma: C/D are 2 packed half2 regs
#define MMA16816H(c, a0,a1,a2,a3, b0,b1) \
    asm volatile("mma.sync.aligned.m16n8k16.row.col.f16.f16.f16.f16 " \
        "{%0,%1}, {%2,%3,%4,%5}, {%6,%7}, {%0,%1};" \
        : "+r"((c)[0]),"+r"((c)[1]) \
        : "r"(a0),"r"(a1),"r"(a2),"r"(a3), "r"(b0),"r"(b1))

// ---------------- kernel 1: state = xc@W_fc + b_fc ----------------
__global__ void k_state(const float* __restrict__ xc, const float* __restrict__ W_fc,
                        const float* __restrict__ b_fc, const float* __restrict__ b_kin) {
    int s = blockIdx.x, j = threadIdx.x;
    __shared__ float xcs[NG];
    if (j < NG) xcs[j] = xc[s*NG + j];
    __syncthreads();
    float acc = b_fc[j];
#pragma unroll
    for (int g = 0; g < NG; g++) acc = fmaf(xcs[g], W_fc[g*HS + j], acc);
    g_zbase[s*HS + j] = acc + b_kin[j];
    g_hg[s*HS + j]    = tanhf(acc);
}

// ---------------- kernel 2: per-site gate params + routing weights ----------------
__global__ void k_params(const float* __restrict__ W_r, const float* __restrict__ b_r,
                         const float* __restrict__ W_g, const float* __restrict__ b_g) {
    int s = blockIdx.x, tid = threadIdx.x;
    __shared__ float hgs[HS];
    __shared__ float pG[144], pR[144];
    hgs[tid] = g_hg[s*HS + tid];
    __syncthreads();
    for (int idx = tid; idx < 288; idx += 256) {
        int o = (idx < 144) ? idx : idx - 144;
        const float* W = (idx < 144) ? W_g : W_r;
        float acc = (idx < 144) ? b_g[o] : b_r[o];
#pragma unroll 8
        for (int k = 0; k < HS; k++) acc = fmaf(hgs[k], W[k*144 + o], acc);
        if (idx < 144) pG[o] = acc; else pR[o] = acc;
    }
    __syncthreads();
    if (tid < NH) {
        int h = tid, gid = s*NH + h;
        g_prm[0][gid] = sigf(pG[0*16+h]);
        g_prm[1][gid] = sigf(pG[1*16+h]);
        g_prm[2][gid] = sigf(pG[2*16+h]);
        g_prm[3][gid] = sigf(pG[3*16+h]);
        float t = sigf(pG[4*16+h]) * 10.f; g_prm[4][gid] = t*t*t;
        g_prm[5][gid] = fmaxf(pG[5*16+h], 0.f) * 0.1f;
        g_prm[6][gid] = fminf(fmaxf(pG[7*16+h]*(1.f/6.f) + 0.5f, 0.f), 1.f) * 0.5f;
        g_prm[7][gid] = fmaxf(pG[8*16+h], 0.f);
        float m = -1e30f;
#pragma unroll
        for (int i = 0; i < 16; i++) m = fmaxf(m, pG[6*16+i]);
        float sum = 0.f;
#pragma unroll
        for (int i = 0; i < 16; i++) sum += expf(pG[6*16+i] - m);
        g_prm[8][gid] = expf(pG[6*16+h] - m) / sum;
        float r[9]; float rm = -1e30f;
#pragma unroll
        for (int i = 0; i < 9; i++) { r[i] = pR[h*9 + i]; rm = fmaxf(rm, r[i]); }
        float rs = 0.f;
#pragma unroll
        for (int i = 0; i < 9; i++) { r[i] = expf(r[i] - rm); rs += r[i]; }
        float inv = 1.f / rs;
        float c = 0.f, w[8], ws = 0.f;
#pragma unroll
        for (int i = 0; i < 8; i++) {
            float si = r[i] * inv; c += si;
            float wi = fminf(c, 1.f - c + si);
            w[i] = wi; ws += wi;
        }
        float wsi = 1.f / ws;
#pragma unroll
        for (int i = 0; i < 8; i++) g_wr[gid*NR + i] = w[i] * wsi;
    }
}

// ---------------- kernel 3: K-param MLP — fused A-compute inside mma loop ----------------
// 128 threads = 4 mma warps; no h smem tile, no in-loop barriers; 4 CTAs/SM.
__global__ void __launch_bounds__(128, 4) k_kparam(
        const float* __restrict__ x, const float* __restrict__ W_kin,
        const float* __restrict__ W_kout, const float* __restrict__ b_kout) {
    extern __shared__ char sm[];
    uint32_t smb = smem_u32(sm);
    uint4* wz4  = (uint4*)(sm + OF_WZ);
    uint32_t* zb2 = (uint32_t*)(sm + OF_ZB2);
    int s = blockIdx.x, tid = threadIdx.x;
    int w = tid >> 5, lane = tid & 31;

    // ---- one-time setup (128 threads) ----
    {
        int k = tid * 2;
        wz4[tid] = make_uint4(
            packh2(W_kin[0*HS+k], W_kin[0*HS+k+1]),
            packh2(W_kin[1*HS+k], W_kin[1*HS+k+1]),
            packh2(W_kin[2*HS+k], W_kin[2*HS+k+1]),
            packh2(W_kin[3*HS+k], W_kin[3*HS+k+1]));
        zb2[tid] = packh2(g_zbase[s*HS+k], g_zbase[s*HS+k+1]);
    }
    for (int idx = tid; idx < HS*NO; idx += 128) {
        int k = idx / NO, n = idx - k*NO;
        *(__half*)(sm + OF_W + n*STRIDE_H + k*2) = __float2half(W_kout[idx]);
    }

    int rq = lane >> 2;   // 0..7  (row within 8-row group)
    int kq = lane & 3;    // 0..3  (k-pair column)
    int l4 = lane & 15;
    uint32_t bm_base = smb + OF_W + (uint32_t)(l4 & 7)*STRIDE_H + (uint32_t)(l4 >> 3)*16;

    uint32_t biasp[6];
#pragma unroll
    for (int nt = 0; nt < 6; nt++) {
        int c0 = nt*8 + kq*2;
        biasp[nt] = packh2(b_kout[c0], b_kout[c0+1]);
    }
    __syncthreads();   // setup visible; no further barriers needed

    for (int tile = 0; tile < NTILES; tile++) {
        int tb = tile * TILE_T;
        // lane's 4 t-rows: r0 = mma a0 row, r1 = a1 row (+8); +64/+72 for m-half 1
        int trow[4];
        trow[0] = tb + w*16 + rq;
        trow[1] = trow[0] + 8;
        trow[2] = trow[0] + 64;
        trow[3] = trow[0] + 72;

        // per-row packed feature broadcasts f16x2: [row][feature]
        uint32_t fr[4][4];
#pragma unroll
        for (int ri = 0; ri < 4; ri++) {
            int t = trow[ri];
            if (t < NT) {
                const float* xr = x + (size_t)(t*NS + s) * 6;
                float2 p01 = *(const float2*)(xr);      // Prcp, Evp
                float2 p23 = *(const float2*)(xr + 2);  // T1, T2
                float2 p45 = *(const float2*)(xr + 4);  // Rad, Hum
                fr[ri][0] = packh2(p23.x, p23.x);
                fr[ri][1] = packh2(p23.y, p23.y);
                fr[ri][2] = packh2(p45.x, p45.x);
                fr[ri][3] = packh2(p45.y, p45.y);
                if (kq == 0) {
                    float fl = fminf(fmaxf(p23.y / (p23.y - p23.x + 1e-5f), 0.f), 1.f);
                    g_Pl[s*NT + t] = p01.x * fl;
                    g_Ps[s*NT + t] = p01.x * (1.f - fl);
                    g_Ev[s*NT + t] = p01.y;
                }
            } else {
                fr[ri][0] = 0; fr[ri][1] = 0; fr[ri][2] = 0; fr[ri][3] = 0;
            }
        }

        uint32_t acc[2][6][2];
#pragma unroll
        for (int nt = 0; nt < 6; nt++) {
            acc[0][nt][0] = biasp[nt]; acc[0][nt][1] = biasp[nt];
            acc[1][nt][0] = biasp[nt]; acc[1][nt][1] = biasp[nt];
        }

#pragma unroll 4
        for (int ks = 0; ks < 16; ks++) {
            int p_lo = ks*8 + kq, p_hi = p_lo + 4;
            uint4 wlo = wz4[p_lo], whi = wz4[p_hi];
            uint32_t zlo = zb2[p_lo], zhi = zb2[p_hi];
            // a fragments: [mhalf][slot]; slot0=(r0,lo) slot1=(r1,lo) slot2=(r0,hi) slot3=(r1,hi)
            uint32_t a[2][4];
#pragma unroll
            for (int mh = 0; mh < 2; mh++) {
#pragma unroll
                for (int rr = 0; rr < 2; rr++) {
                    int ri = mh*2 + rr;
                    uint32_t z0 = zlo;
                    HFMA2(z0, wlo.x, fr[ri][0]);
                    HFMA2(z0, wlo.y, fr[ri][1]);
                    HFMA2(z0, wlo.z, fr[ri][2]);
                    HFMA2(z0, wlo.w, fr[ri][3]);
                    TANH2(a[mh][rr], z0);
                    uint32_t z1 = zhi;
                    HFMA2(z1, whi.x, fr[ri][0]);
                    HFMA2(z1, whi.y, fr[ri][1]);
                    HFMA2(z1, whi.z, fr[ri][2]);
                    HFMA2(z1, whi.w, fr[ri][3]);
                    TANH2(a[mh][2+rr], z1);
                }
            }
            uint32_t koff = (uint32_t)ks * 32;
#pragma unroll
            for (int nt = 0; nt < 6; nt++) {
                uint32_t b0, b1;
                LDMATRIX_X2(b0, b1, bm_base + (uint32_t)(nt*8)*STRIDE_H + koff);
                MMA16816H(acc[0][nt], a[0][0], a[0][1], a[0][2], a[0][3], b0, b1);
                MMA16816H(acc[1][nt], a[1][0], a[1][1], a[1][2], a[1][3], b0, b1);
            }
        }

        // epilogue: both m-halves -> transposed fp16 [s][c][t]
#pragma unroll
        for (int half = 0; half < 2; half++) {
            int t0 = trow[half*2];
            int t1 = trow[half*2 + 1];
#pragma unroll
            for (int nt = 0; nt < 6; nt++) {
                int c0 = nt*8 + kq*2;
                int grp = c0 >> 4;            // 0 km(exp), 1 ki(relu), 2 ke(exp)
                __half2 p0h = *reinterpret_cast<__half2*>(&acc[half][nt][0]);
                __half2 p1h = *reinterpret_cast<__half2*>(&acc[half][nt][1]);
                float v00 = __low2float(p0h), v01 = __high2float(p0h);
                float v10 = __low2float(p1h), v11 = __high2float(p1h);
                if (grp == 1) {
                    v00 = fmaxf(v00, 0.f); v01 = fmaxf(v01, 0.f);
                    v10 = fmaxf(v10, 0.f); v11 = fmaxf(v11, 0.f);
                } else {
                    v00 = __expf(v00); v01 = __expf(v01);
                    v10 = __expf(v10); v11 = __expf(v11);
                }
                __half* r0 = g_k3 + ((size_t)s*48 + c0)*NT;
                __half* r1 = r0 + NT;
                if (t0 < NT) { r0[t0] = __float2half(v00); r1[t0] = __float2half(v01); }
                if (t1 < NT) { r0[t1] = __float2half(v10); r1[t1] = __float2half(v11); }
            }
        }
    }
}

// ---------------- kernel 4: fused scan — R10-proven structure, 64-thread blocks ----------------
__global__ void __launch_bounds__(64) k_scan(float* __restrict__ out) {
    int gid = blockIdx.x * blockDim.x + threadIdx.x;   // = s*NH + h
    int site = gid >> 4, h = gid & 15;
    float kp = g_prm[0][gid], ksg = g_prm[1][gid], kd = g_prm[2][gid];
    float gd = g_prm[3][gid], gl = g_prm[4][gid], qb = g_prm[5][gid];
    float gi = g_prm[6][gid], ge = g_prm[7][gid], ga = g_prm[8][gid];
    const float4* wrp = (const float4*)(g_wr + gid*NR);
    float4 wa = wrp[0], wb = wrp[1];
    float wrv[8] = {wa.x, wa.y, wa.z, wa.w, wb.x, wb.y, wb.z, wb.w};

    float A[8];
#pragma unroll
    for (int j = 0; j < 8; j++) A[j] = 0.f;
    float Sf = 0.f, Ss = 0.f, Sg = 0.f;

    const uint4* pkm = (const uint4*)(g_k3 + ((size_t)site*48 + h)*NT);
    const uint4* pki = (const uint4*)(g_k3 + ((size_t)site*48 + 16 + h)*NT);
    const uint4* pke = (const uint4*)(g_k3 + ((size_t)site*48 + 32 + h)*NT);
    const float4* pPs = (const float4*)(g_Ps + site*NT);
    const float4* pPl = (const float4*)(g_Pl + site*NT);
    const float4* pEv = (const float4*)(g_Ev + site*NT);

    uint4 ckm = pkm[0], cki = pki[0], cke = pke[0];
    float4 cPs0 = pPs[0], cPs1 = pPs[1];
    float4 cPl0 = pPl[0], cPl1 = pPl[1];
    float4 cEv0 = pEv[0], cEv1 = pEv[1];

#pragma unroll 2
    for (int blk = 0; blk < NBLK; blk++) {
        uint4 nkm, nki, nke;
        float4 nPs0, nPs1, nPl0, nPl1, nEv0, nEv1;
        if (blk + 1 < NBLK) {
            nkm = pkm[blk+1]; nki = pki[blk+1]; nke = pke[blk+1];
            nPs0 = pPs[2*blk+2]; nPs1 = pPs[2*blk+3];
            nPl0 = pPl[2*blk+2]; nPl1 = pPl[2*blk+3];
            nEv0 = pEv[2*blk+2]; nEv1 = pEv[2*blk+3];
        }
        int tbase = blk * 8;
#pragma unroll
        for (int i = 0; i < 8; i++) {
            int tc = tbase + i;
            float kmt = geth(ckm, i), kit = geth(cki, i), ket = geth(cke, i);
            float Pst = getf(cPs0, cPs1, i);
            float Plt = getf(cPl0, cPl1, i);
            float Evt = getf(cEv0, cEv1, i);

            Sf += Pst;
            float qf = fminf(Sf, kmt); Sf -= qf;
            float inflow = qf + Plt;
            float qd = inflow * gi;
            Ss += inflow * (1.f - gi);
            float E = fminf(fmaxf(Ss, 0.f), Evt * ket * ge); Ss -= E;
            float qi = fminf(kit, fmaxf(Ss, 0.f)); Ss -= qi;
            float qp = kp * fmaxf(Ss - gl, 0.f);
            float qsa = ksg * fminf(fmaxf(Ss, 0.f), gl);
            Ss -= qp + qsa;
            Sg += qsa * gd;
            float qg = fmaf(kd, Sg, qb); Sg *= (1.f - kd);
            float q = qp + qsa * (1.f - gd) + qg + qd + qi;

#pragma unroll
            for (int j = 0; j < 8; j++) A[j] = fmaf(q, wrv[j], A[j]);

            if (tc >= NR - 1) {
                float v = A[0] * ga;
                v += __shfl_xor_sync(0xffffffffu, v, 1);
                v += __shfl_xor_sync(0xffffffffu, v, 2);
                v += __shfl_xor_sync(0xffffffffu, v, 4);
                v += __shfl_xor_sync(0xffffffffu, v, 8);
                if (h == 0) out[(tc - (NR-1))*NS + site] = v;
            }
#pragma unroll
            for (int j = 0; j < 7; j++) A[j] = A[j+1];
            A[7] = 0.f;
        }
        if (blk + 1 < NBLK) {
            ckm = nkm; cki = nki; cke = nke;
            cPs0 = nPs0; cPs1 = nPs1;
            cPl0 = nPl0; cPl1 = nPl1;
            cEv0 = nEv0; cEv1 = nEv1;
        }
    }
}

// ---------------- launch ----------------
extern "C" void kernel_launch(void* const* d_in, const int* in_sizes, int n_in,
                              void* d_out, int out_size) {
    const float* x      = (const float*)d_in[0];
    const float* xc     = (const float*)d_in[1];
    const float* W_fc   = (const float*)d_in[2];
    const float* b_fc   = (const float*)d_in[3];
    const float* W_r    = (const float*)d_in[4];
    const float* b_r    = (const float*)d_in[5];
    const float* W_g    = (const float*)d_in[6];
    const float* b_g    = (const float*)d_in[7];
    const float* W_kin  = (const float*)d_in[8];
    const float* b_kin  = (const float*)d_in[9];
    const float* W_kout = (const float*)d_in[10];
    const float* b_kout = (const float*)d_in[11];
    float* out = (float*)d_out;

    k_state<<<NS, HS>>>(xc, W_fc, b_fc, b_kin);
    k_params<<<NS, 256>>>(W_r, b_r, W_g, b_g);

    cudaFuncSetAttribute(k_kparam, cudaFuncAttributeMaxDynamicSharedMemorySize, SMEM_BYTES);
    k_kparam<<<NS, 128, SMEM_BYTES>>>(x, W_kin, W_kout, b_kout);

    k_scan<<<(NS*NH)/64, 64>>>(out);
}

// round 14
// speedup vs baseline: 1.5923x; 1.0247x over previous
#include <cuda_runtime.h>
#include <cuda_bf16.h>
#include <cuda_fp16.h>
#include <cstdint>

#define NT   1000
#define NS   2048
#define NH   16
#define NR   8
#define HS   256
#define NG   32
#define NO   48
#define NSNH (NS*NH)
#define TILE_T 128
#define NTILES 8
#define NBLK (NT/8)           // 125
#define STRIDE_H 560          // bytes per 256-fp16 row (conflict-free ldmatrix)

// ---- dynamic smem byte layout (k_kparam) ----
#define OF_W   0                              // 48 x 560 = 26880
#define OF_WZ  26880                          // 128 x uint4 (packed W_kin half2 pairs)
#define OF_ZB2 (OF_WZ + 128*16)               // 28928, 128 x uint (packed zbase half2)
#define SMEM_BYTES (OF_ZB2 + 512 + 128)       // 29568 -> 4 CTAs/SM

// ---------------- device scratch ----------------
__device__ float g_zbase[NS*HS];
__device__ float g_hg[NS*HS];
__device__ float g_prm[9][NSNH];
__device__ float g_wr[NSNH*NR];
__device__ __half g_k3[(size_t)NS*48*NT];  // [s][c][t]: c 0..15 km, 16..31 ki, 32..47 ke
__device__ float g_Ps[NS*NT];              // [s][t]
__device__ float g_Pl[NS*NT];
__device__ float g_Ev[NS*NT];

__device__ __forceinline__ uint32_t smem_u32(const void* p) {
    uint32_t a;
    asm("{ .reg .u64 t; cvta.to.shared.u64 t, %1; cvt.u32.u64 %0, t; }" : "=r"(a) : "l"(p));
    return a;
}
__device__ __forceinline__ float sigf(float v) { return 1.f / (1.f + expf(-v)); }
__device__ __forceinline__ uint32_t packh2(float a, float b) {
    __half2 p = __floats2half2_rn(a, b);
    return *reinterpret_cast<uint32_t*>(&p);
}
__device__ __forceinline__ float geth(const uint4& v, int i) {
    uint32_t w = (i < 2) ? v.x : (i < 4) ? v.y : (i < 6) ? v.z : v.w;
    __half2 h2 = *reinterpret_cast<const __half2*>(&w);
    return (i & 1) ? __high2float(h2) : __low2float(h2);
}
__device__ __forceinline__ float getf(const float4& a, const float4& b, int i) {
    const float4& v = (i < 4) ? a : b;
    int j = i & 3;
    return (j == 0) ? v.x : (j == 1) ? v.y : (j == 2) ? v.z : v.w;
}

#define HFMA2(z, w, f) asm("fma.rn.f16x2 %0, %1, %2, %0;" : "+r"(z) : "r"(w), "r"(f))
#define TANH2(d, z)    asm("tanh.approx.f16x2 %0, %1;" : "=r"(d) : "r"(z))

#define LDMATRIX_X2(r0,r1, addr) \
    asm volatile("ldmatrix.sync.aligned.m8n8.x2.shared.b16 {%0,%1}, [%2];" \
        : "=r"(r0),"=r"(r1) : "r"(addr))

// fp16-accumulate mma: C/D are 2 packed half2 regs
#define MMA16816H(c, a0,a1,a2,a3, b0,b1) \
    asm volatile("mma.sync.aligned.m16n8k16.row.col.f16.f16.f16.f16 " \
        "{%0,%1}, {%2,%3,%4,%5}, {%6,%7}, {%0,%1};" \
        : "+r"((c)[0]),"+r"((c)[1]) \
        : "r"(a0),"r"(a1),"r"(a2),"r"(a3), "r"(b0),"r"(b1))

// compute the 8 packed a-fragments for one ks group
__device__ __forceinline__ void comp_a(
        const uint4* __restrict__ wz4, const uint32_t* __restrict__ zb2,
        int ks, int kq, const uint32_t fr[4][4], uint32_t a[2][4]) {
    int p_lo = ks*8 + kq, p_hi = p_lo + 4;
    uint4 wlo = wz4[p_lo], whi = wz4[p_hi];
    uint32_t zlo = zb2[p_lo], zhi = zb2[p_hi];
#pragma unroll
    for (int mh = 0; mh < 2; mh++) {
#pragma unroll
        for (int rr = 0; rr < 2; rr++) {
            int ri = mh*2 + rr;
            uint32_t z0 = zlo;
            HFMA2(z0, wlo.x, fr[ri][0]);
            HFMA2(z0, wlo.y, fr[ri][1]);
            HFMA2(z0, wlo.z, fr[ri][2]);
            HFMA2(z0, wlo.w, fr[ri][3]);
            TANH2(a[mh][rr], z0);
            uint32_t z1 = zhi;
            HFMA2(z1, whi.x, fr[ri][0]);
            HFMA2(z1, whi.y, fr[ri][1]);
            HFMA2(z1, whi.z, fr[ri][2]);
            HFMA2(z1, whi.w, fr[ri][3]);
            TANH2(a[mh][2+rr], z1);
        }
    }
}

// ---------------- kernel 1: state = xc@W_fc + b_fc ----------------
__global__ void k_state(const float* __restrict__ xc, const float* __restrict__ W_fc,
                        const float* __restrict__ b_fc, const float* __restrict__ b_kin) {
    int s = blockIdx.x, j = threadIdx.x;
    __shared__ float xcs[NG];
    if (j < NG) xcs[j] = xc[s*NG + j];
    __syncthreads();
    float acc = b_fc[j];
#pragma unroll
    for (int g = 0; g < NG; g++) acc = fmaf(xcs[g], W_fc[g*HS + j], acc);
    g_zbase[s*HS + j] = acc + b_kin[j];
    g_hg[s*HS + j]    = tanhf(acc);
}

// ---------------- kernel 2: gate params + routing weights, 4 sites/block ----------------
__global__ void k_params(const float* __restrict__ W_r, const float* __restrict__ b_r,
                         const float* __restrict__ W_g, const float* __restrict__ b_g) {
    int s0 = blockIdx.x * 4, tid = threadIdx.x;
    __shared__ float hgs[4][HS];
    __shared__ float pG[4][144], pR[4][144];
    for (int i = tid; i < 4*HS; i += 256)
        hgs[i >> 8][i & 255] = g_hg[(s0 + (i >> 8))*HS + (i & 255)];
    __syncthreads();
    for (int idx = tid; idx < 288; idx += 256) {
        int o = (idx < 144) ? idx : idx - 144;
        const float* W = (idx < 144) ? W_g : W_r;
        float b = (idx < 144) ? b_g[o] : b_r[o];
        float a0 = b, a1 = b, a2 = b, a3 = b;
#pragma unroll 8
        for (int k = 0; k < HS; k++) {
            float wv = W[k*144 + o];
            a0 = fmaf(hgs[0][k], wv, a0);
            a1 = fmaf(hgs[1][k], wv, a1);
            a2 = fmaf(hgs[2][k], wv, a2);
            a3 = fmaf(hgs[3][k], wv, a3);
        }
        if (idx < 144) { pG[0][o]=a0; pG[1][o]=a1; pG[2][o]=a2; pG[3][o]=a3; }
        else           { pR[0][o]=a0; pR[1][o]=a1; pR[2][o]=a2; pR[3][o]=a3; }
    }
    __syncthreads();
    if (tid < 64) {
        int si = tid >> 4, h = tid & 15;
        int gid = (s0 + si)*NH + h;
        const float* G = pG[si];
        const float* R = pR[si];
        g_prm[0][gid] = sigf(G[0*16+h]);
        g_prm[1][gid] = sigf(G[1*16+h]);
        g_prm[2][gid] = sigf(G[2*16+h]);
        g_prm[3][gid] = sigf(G[3*16+h]);
        float t = sigf(G[4*16+h]) * 10.f; g_prm[4][gid] = t*t*t;
        g_prm[5][gid] = fmaxf(G[5*16+h], 0.f) * 0.1f;
        g_prm[6][gid] = fminf(fmaxf(G[7*16+h]*(1.f/6.f) + 0.5f, 0.f), 1.f) * 0.5f;
        g_prm[7][gid] = fmaxf(G[8*16+h], 0.f);
        float m = -1e30f;
#pragma unroll
        for (int i = 0; i < 16; i++) m = fmaxf(m, G[6*16+i]);
        float sum = 0.f;
#pragma unroll
        for (int i = 0; i < 16; i++) sum += expf(G[6*16+i] - m);
        g_prm[8][gid] = expf(G[6*16+h] - m) / sum;
        float r[9]; float rm = -1e30f;
#pragma unroll
        for (int i = 0; i < 9; i++) { r[i] = R[h*9 + i]; rm = fmaxf(rm, r[i]); }
        float rs = 0.f;
#pragma unroll
        for (int i = 0; i < 9; i++) { r[i] = expf(r[i] - rm); rs += r[i]; }
        float inv = 1.f / rs;
        float c = 0.f, w[8], ws = 0.f;
#pragma unroll
        for (int i = 0; i < 8; i++) {
            float si2 = r[i] * inv; c += si2;
            float wi = fminf(c, 1.f - c + si2);
            w[i] = wi; ws += wi;
        }
        float wsi = 1.f / ws;
#pragma unroll
        for (int i = 0; i < 8; i++) g_wr[gid*NR + i] = w[i] * wsi;
    }
}

// ---------------- kernel 3: K-param MLP — fused A-compute, ks software pipeline ----------------
__global__ void __launch_bounds__(128, 4) k_kparam(
        const float* __restrict__ x, const float* __restrict__ W_kin,
        const float* __restrict__ W_kout, const float* __restrict__ b_kout) {
    extern __shared__ char sm[];
    uint32_t smb = smem_u32(sm);
    uint4* wz4  = (uint4*)(sm + OF_WZ);
    uint32_t* zb2 = (uint32_t*)(sm + OF_ZB2);
    int s = blockIdx.x, tid = threadIdx.x;
    int w = tid >> 5, lane = tid & 31;

    // ---- one-time setup (128 threads) ----
    {
        int k = tid * 2;
        wz4[tid] = make_uint4(
            packh2(W_kin[0*HS+k], W_kin[0*HS+k+1]),
            packh2(W_kin[1*HS+k], W_kin[1*HS+k+1]),
            packh2(W_kin[2*HS+k], W_kin[2*HS+k+1]),
            packh2(W_kin[3*HS+k], W_kin[3*HS+k+1]));
        zb2[tid] = packh2(g_zbase[s*HS+k], g_zbase[s*HS+k+1]);
    }
    for (int idx = tid; idx < HS*NO; idx += 128) {
        int k = idx / NO, n = idx - k*NO;
        *(__half*)(sm + OF_W + n*STRIDE_H + k*2) = __float2half(W_kout[idx]);
    }

    int rq = lane >> 2;   // 0..7
    int kq = lane & 3;    // 0..3
    int l4 = lane & 15;
    uint32_t bm_base = smb + OF_W + (uint32_t)(l4 & 7)*STRIDE_H + (uint32_t)(l4 >> 3)*16;

    uint32_t biasp[6];
#pragma unroll
    for (int nt = 0; nt < 6; nt++) {
        int c0 = nt*8 + kq*2;
        biasp[nt] = packh2(b_kout[c0], b_kout[c0+1]);
    }
    __syncthreads();   // setup visible; no further barriers needed

    for (int tile = 0; tile < NTILES; tile++) {
        int tb = tile * TILE_T;
        int trow[4];
        trow[0] = tb + w*16 + rq;
        trow[1] = trow[0] + 8;
        trow[2] = trow[0] + 64;
        trow[3] = trow[0] + 72;

        uint32_t fr[4][4];
#pragma unroll
        for (int ri = 0; ri < 4; ri++) {
            int t = trow[ri];
            if (t < NT) {
                const float* xr = x + (size_t)(t*NS + s) * 6;
                float2 p01 = *(const float2*)(xr);      // Prcp, Evp
                float2 p23 = *(const float2*)(xr + 2);  // T1, T2
                float2 p45 = *(const float2*)(xr + 4);  // Rad, Hum
                fr[ri][0] = packh2(p23.x, p23.x);
                fr[ri][1] = packh2(p23.y, p23.y);
                fr[ri][2] = packh2(p45.x, p45.x);
                fr[ri][3] = packh2(p45.y, p45.y);
                if (kq == 0) {
                    float fl = fminf(fmaxf(p23.y / (p23.y - p23.x + 1e-5f), 0.f), 1.f);
                    g_Pl[s*NT + t] = p01.x * fl;
                    g_Ps[s*NT + t] = p01.x * (1.f - fl);
                    g_Ev[s*NT + t] = p01.y;
                }
            } else {
                fr[ri][0] = 0; fr[ri][1] = 0; fr[ri][2] = 0; fr[ri][3] = 0;
            }
        }

        uint32_t acc[2][6][2];
#pragma unroll
        for (int nt = 0; nt < 6; nt++) {
            acc[0][nt][0] = biasp[nt]; acc[0][nt][1] = biasp[nt];
            acc[1][nt][0] = biasp[nt]; acc[1][nt][1] = biasp[nt];
        }

        // ks software pipeline: compute a(ks+1) while issuing MMAs for ks
        uint32_t aC[2][4], aN[2][4];
        comp_a(wz4, zb2, 0, kq, fr, aC);
#pragma unroll
        for (int ks = 0; ks < 16; ks++) {
            if (ks < 15) comp_a(wz4, zb2, ks+1, kq, fr, aN);
            uint32_t koff = (uint32_t)ks * 32;
#pragma unroll
            for (int nt = 0; nt < 6; nt++) {
                uint32_t b0, b1;
                LDMATRIX_X2(b0, b1, bm_base + (uint32_t)(nt*8)*STRIDE_H + koff);
                MMA16816H(acc[0][nt], aC[0][0], aC[0][1], aC[0][2], aC[0][3], b0, b1);
                MMA16816H(acc[1][nt], aC[1][0], aC[1][1], aC[1][2], aC[1][3], b0, b1);
            }
            if (ks < 15) {
#pragma unroll
                for (int mh = 0; mh < 2; mh++)
#pragma unroll
                    for (int q = 0; q < 4; q++) aC[mh][q] = aN[mh][q];
            }
        }

        // epilogue: both m-halves -> transposed fp16 [s][c][t]
#pragma unroll
        for (int half = 0; half < 2; half++) {
            int t0 = trow[half*2];
            int t1 = trow[half*2 + 1];
#pragma unroll
            for (int nt = 0; nt < 6; nt++) {
                int c0 = nt*8 + kq*2;
                int grp = c0 >> 4;            // 0 km(exp), 1 ki(relu), 2 ke(exp)
                __half2 p0h = *reinterpret_cast<__half2*>(&acc[half][nt][0]);
                __half2 p1h = *reinterpret_cast<__half2*>(&acc[half][nt][1]);
                float v00 = __low2float(p0h), v01 = __high2float(p0h);
                float v10 = __low2float(p1h), v11 = __high2float(p1h);
                if (grp == 1) {
                    v00 = fmaxf(v00, 0.f); v01 = fmaxf(v01, 0.f);
                    v10 = fmaxf(v10, 0.f); v11 = fmaxf(v11, 0.f);
                } else {
                    v00 = __expf(v00); v01 = __expf(v01);
                    v10 = __expf(v10); v11 = __expf(v11);
                }
                __half* r0 = g_k3 + ((size_t)s*48 + c0)*NT;
                __half* r1 = r0 + NT;
                if (t0 < NT) { r0[t0] = __float2half(v00); r1[t0] = __float2half(v01); }
                if (t1 < NT) { r0[t1] = __float2half(v10); r1[t1] = __float2half(v11); }
            }
        }
    }
}

// ---------------- kernel 4: fused scan — R10-proven structure, 64-thread blocks ----------------
__global__ void __launch_bounds__(64) k_scan(float* __restrict__ out) {
    int gid = blockIdx.x * blockDim.x + threadIdx.x;   // = s*NH + h
    int site = gid >> 4, h = gid & 15;
    float kp = g_prm[0][gid], ksg = g_prm[1][gid], kd = g_prm[2][gid];
    float gd = g_prm[3][gid], gl = g_prm[4][gid], qb = g_prm[5][gid];
    float gi = g_prm[6][gid], ge = g_prm[7][gid], ga = g_prm[8][gid];
    const float4* wrp = (const float4*)(g_wr + gid*NR);
    float4 wa = wrp[0], wb = wrp[1];
    float wrv[8] = {wa.x, wa.y, wa.z, wa.w, wb.x, wb.y, wb.z, wb.w};

    float A[8];
#pragma unroll
    for (int j = 0; j < 8; j++) A[j] = 0.f;
    float Sf = 0.f, Ss = 0.f, Sg = 0.f;

    const uint4* pkm = (const uint4*)(g_k3 + ((size_t)site*48 + h)*NT);
    const uint4* pki = (const uint4*)(g_k3 + ((size_t)site*48 + 16 + h)*NT);
    const uint4* pke = (const uint4*)(g_k3 + ((size_t)site*48 + 32 + h)*NT);
    const float4* pPs = (const float4*)(g_Ps + site*NT);
    const float4* pPl = (const float4*)(g_Pl + site*NT);
    const float4* pEv = (const float4*)(g_Ev + site*NT);

    uint4 ckm = pkm[0], cki = pki[0], cke = pke[0];
    float4 cPs0 = pPs[0], cPs1 = pPs[1];
    float4 cPl0 = pPl[0], cPl1 = pPl[1];
    float4 cEv0 = pEv[0], cEv1 = pEv[1];

#pragma unroll 2
    for (int blk = 0; blk < NBLK; blk++) {
        uint4 nkm, nki, nke;
        float4 nPs0, nPs1, nPl0, nPl1, nEv0, nEv1;
        if (blk + 1 < NBLK) {
            nkm = pkm[blk+1]; nki = pki[blk+1]; nke = pke[blk+1];
            nPs0 = pPs[2*blk+2]; nPs1 = pPs[2*blk+3];
            nPl0 = pPl[2*blk+2]; nPl1 = pPl[2*blk+3];
            nEv0 = pEv[2*blk+2]; nEv1 = pEv[2*blk+3];
        }
        int tbase = blk * 8;
#pragma unroll
        for (int i = 0; i < 8; i++) {
            int tc = tbase + i;
            float kmt = geth(ckm, i), kit = geth(cki, i), ket = geth(cke, i);
            float Pst = getf(cPs0, cPs1, i);
            float Plt = getf(cPl0, cPl1, i);
            float Evt = getf(cEv0, cEv1, i);

            Sf += Pst;
            float qf = fminf(Sf, kmt); Sf -= qf;
            float inflow = qf + Plt;
            float qd = inflow * gi;
            Ss += inflow * (1.f - gi);
            float E = fminf(fmaxf(Ss, 0.f), Evt * ket * ge); Ss -= E;
            float qi = fminf(kit, fmaxf(Ss, 0.f)); Ss -= qi;
            float qp = kp * fmaxf(Ss - gl, 0.f);
            float qsa = ksg * fminf(fmaxf(Ss, 0.f), gl);
            Ss -= qp + qsa;
            Sg += qsa * gd;
            float qg = fmaf(kd, Sg, qb); Sg *= (1.f - kd);
            float q = qp + qsa * (1.f - gd) + qg + qd + qi;

#pragma unroll
            for (int j = 0; j < 8; j++) A[j] = fmaf(q, wrv[j], A[j]);

            if (tc >= NR - 1) {
                float v = A[0] * ga;
                v += __shfl_xor_sync(0xffffffffu, v, 1);
                v += __shfl_xor_sync(0xffffffffu, v, 2);
                v += __shfl_xor_sync(0xffffffffu, v, 4);
                v += __shfl_xor_sync(0xffffffffu, v, 8);
                if (h == 0) out[(tc - (NR-1))*NS + site] = v;
            }
#pragma unroll
            for (int j = 0; j < 7; j++) A[j] = A[j+1];
            A[7] = 0.f;
        }
        if (blk + 1 < NBLK) {
            ckm = nkm; cki = nki; cke = nke;
            cPs0 = nPs0; cPs1 = nPs1;
            cPl0 = nPl0; cPl1 = nPl1;
            cEv0 = nEv0; cEv1 = nEv1;
        }
    }
}

// ---------------- launch ----------------
extern "C" void kernel_launch(void* const* d_in, const int* in_sizes, int n_in,
                              void* d_out, int out_size) {
    const float* x      = (const float*)d_in[0];
    const float* xc     = (const float*)d_in[1];
    const float* W_fc   = (const float*)d_in[2];
    const float* b_fc   = (const float*)d_in[3];
    const float* W_r    = (const float*)d_in[4];
    const float* b_r    = (const float*)d_in[5];
    const float* W_g    = (const float*)d_in[6];
    const float* b_g    = (const float*)d_in[7];
    const float* W_kin  = (const float*)d_in[8];
    const float* b_kin  = (const float*)d_in[9];
    const float* W_kout = (const float*)d_in[10];
    const float* b_kout = (const float*)d_in[11];
    float* out = (float*)d_out;

    k_state<<<NS, HS>>>(xc, W_fc, b_fc, b_kin);
    k_params<<<NS/4, 256>>>(W_r, b_r, W_g, b_g);

    cudaFuncSetAttribute(k_kparam, cudaFuncAttributeMaxDynamicSharedMemorySize, SMEM_BYTES);
    k_kparam<<<NS, 128, SMEM_BYTES>>>(x, W_kin, W_kout, b_kout);

    k_scan<<<(NS*NH)/64, 64>>>(out);
}